// round 15
// baseline (speedup 1.0000x reference)
#include <cuda_runtime.h>
#include <cuda_fp16.h>
#include <math.h>
#include <stdint.h>

static constexpr int N_ = 50000;
static constexpr int E_ = 200000;

// ---------------- scratch ----------------
__device__ __half  g_X2   [(size_t)N_ * 512];   // [hi|lo] fp16 split of [nf|mem]
__device__ float   g_h    [(size_t)N_ * 256];
__device__ __half  g_h2   [(size_t)N_ * 512];   // [hi|lo] split of h
__device__ float   g_qp   [(size_t)N_ * 576];   // [Q'(256)|P(320)] per node
__device__ __half  g_K2   [(size_t)N_ * 256];   // K' fp16 (bias folded)
__device__ float   g_agg2 [(size_t)N_ * 256];
__device__ __half  g_aggc [(size_t)N_ * 704];   // [aggm hi80|lo80|pad32 | aggh hi256 | aggh lo256]
__device__ float   g_nrm  [N_];
__device__ float   g_Wall [2 * 1152 * 256];     // fp32 [Wk;Wv;Wq;Wfused]
__device__ __half  g_Wkqp2[2 * 832 * 512];      // dup fp16 [Wk;Wq;Wfused]
__device__ float   g_bias_kqp[2 * 832];         // [bk|bq_eff|cb]
__device__ float   g_bias_v  [2 * 256];         // bv
__device__ __half  g_Win2 [256 * 512];
__device__ float   g_Wev  [2 * 256 * 80];
__device__ __half  g_WevV2[2 * 256 * 704];      // [Wev|Wev|0 | Wv | Wv]
__device__ __half  g_Wout2[64 * 512];
__device__ float   g_b    [2 * 768];            // [bk|bv|bq_eff]
// CSR
__device__ int g_off [N_ + 1];
__device__ int g_cnt [N_];
__device__ int g_eid [E_];

// ---------------- ptx helpers (family-safe, sm_80 baseline) ----------------
__device__ __forceinline__ uint32_t smem_u32(const void* p) {
    uint32_t a;
    asm("{ .reg .u64 t; cvta.to.shared.u64 t, %1; cvt.u32.u64 %0, t; }" : "=r"(a) : "l"(p));
    return a;
}
__device__ __forceinline__ void cp16(uint32_t dst, const void* src, int pred) {
    asm volatile(
        "{\n\t.reg .pred p;\n\t"
        "setp.ne.u32 p, %2, 0;\n\t"
        "@p cp.async.ca.shared.global [%0], [%1], 16;\n\t"
        "@!p cp.async.ca.shared.global [%0], [%1], 16, 0;\n\t}"
        :: "r"(dst), "l"(src), "r"(pred) : "memory");
}
__device__ __forceinline__ void cp_commit() {
    asm volatile("cp.async.commit_group;" ::: "memory");
}
__device__ __forceinline__ void ldm4(uint32_t* r, uint32_t addr) {
    asm volatile("ldmatrix.sync.aligned.m8n8.x4.shared.b16 {%0,%1,%2,%3}, [%4];"
                 : "=r"(r[0]), "=r"(r[1]), "=r"(r[2]), "=r"(r[3]) : "r"(addr));
}
__device__ __forceinline__ void mma16816(float* c, const uint32_t* a, const uint32_t* b) {
    asm volatile(
        "mma.sync.aligned.m16n8k16.row.col.f32.f16.f16.f32 "
        "{%0,%1,%2,%3},{%4,%5,%6,%7},{%8,%9},{%0,%1,%2,%3};"
        : "+f"(c[0]), "+f"(c[1]), "+f"(c[2]), "+f"(c[3])
        : "r"(a[0]), "r"(a[1]), "r"(a[2]), "r"(a[3]), "r"(b[0]), "r"(b[1]));
}

// ---------------- mma.sync GEMM (double-buffered, K chunks of 64) ----------------
// MODE 0: plain fp32 C.  MODE 1: fp32 C + fp16 [hi|lo] split into S2.
// MODE 2 (KQP): col<256 -> fp16 into S2 (K'); col>=256 -> fp32 C at col-256 (Q'|P).
static constexpr int GSAS = 72;
static constexpr int GSEG = 128 * GSAS;
static constexpr int GSMEM_BYTES = 4 * GSEG * 2;  // 73728

template <int MODE, bool GELU>
__global__ __launch_bounds__(256)
void mma_gemm(const __half* __restrict__ A2, int lda, int klen,
              const __half* __restrict__ W2, int ldw, int noutW,
              const float* __restrict__ bias,
              float* __restrict__ C, int ldc, int M, int noutC,
              __half* __restrict__ S2) {
    extern __shared__ __align__(16) __half smem[];
    int tid = threadIdx.x, lane = tid & 31, wid = tid >> 5;
    int wm = wid & 1, wn = wid >> 1;
    int bm = blockIdx.x * 128, bn = blockIdx.y * 128;
    int NC = klen >> 6;
    uint32_t sU = smem_u32(smem);

    int arow = (lane & 7) + ((lane >> 3) & 1) * 8;
    int acol = ((lane >> 4) & 1) * 8;
    int bco  = ((lane >> 4) & 1) * 8 + (lane & 7);
    int bko  = ((lane >> 3) & 1) * 8;

    float acc[4][4][4] = {};

#define LOADC(c, buf)                                                                    \
    {                                                                                    \
        int _c64 = (c) * 64;                                                             \
        uint32_t _ab = sU + (buf) * (2 * GSEG * 2);                                      \
        uint32_t _bb = _ab + GSEG * 2;                                                   \
        _Pragma("unroll")                                                                \
        for (int _k = 0; _k < 4; _k++) {                                                 \
            int _id = tid + _k * 256;                                                    \
            int _r = _id >> 3, _cg = (_id & 7) * 8;                                      \
            uint32_t _so = (uint32_t)(_r * GSAS + _cg) * 2;                              \
            int _gr = bm + _r; int _pa = _gr < M; int _ga = _pa ? _gr : 0;               \
            cp16(_ab + _so, A2 + (size_t)_ga * lda + _c64 + _cg, _pa);                   \
            int _wr = bn + _r; int _pb = _wr < noutW; int _wa = _pb ? _wr : 0;           \
            cp16(_bb + _so, W2 + (size_t)_wa * ldw + _c64 + _cg, _pb);                   \
        }                                                                                \
        cp_commit();                                                                     \
    }

    LOADC(0, 0);
    for (int c = 0; c < NC; c++) {
        if (c + 1 < NC) {
            LOADC(c + 1, (c + 1) & 1);
            asm volatile("cp.async.wait_group 1;" ::: "memory");
        } else {
            asm volatile("cp.async.wait_group 0;" ::: "memory");
        }
        __syncthreads();
        uint32_t sAb = sU + (c & 1) * (2 * GSEG * 2);
        uint32_t sBb = sAb + GSEG * 2;
#pragma unroll
        for (int ks = 0; ks < 4; ks++) {
            uint32_t af[4][4];
#pragma unroll
            for (int mf = 0; mf < 4; mf++)
                ldm4(af[mf], sAb + (uint32_t)((wm * 64 + mf * 16 + arow) * GSAS + ks * 16 + acol) * 2);
            uint32_t bf[4][2];
#pragma unroll
            for (int p = 0; p < 2; p++) {
                uint32_t r4[4];
                ldm4(r4, sBb + (uint32_t)((wn * 32 + p * 16 + bco) * GSAS + ks * 16 + bko) * 2);
                bf[2 * p][0] = r4[0]; bf[2 * p][1] = r4[1];
                bf[2 * p + 1][0] = r4[2]; bf[2 * p + 1][1] = r4[3];
            }
#pragma unroll
            for (int mf = 0; mf < 4; mf++)
#pragma unroll
                for (int nf = 0; nf < 4; nf++)
                    mma16816(acc[mf][nf], af[mf], bf[nf]);
        }
        __syncthreads();
    }
#undef LOADC

    int cr = lane >> 2, cc = (lane & 3) * 2;
#pragma unroll
    for (int mf = 0; mf < 4; mf++) {
#pragma unroll
        for (int nf = 0; nf < 4; nf++) {
            int col = bn + wn * 32 + nf * 8 + cc;
            if (col >= noutC) continue;
            float bz0 = bias ? bias[col] : 0.f;
            float bz1 = bias ? bias[col + 1] : 0.f;
#pragma unroll
            for (int hh = 0; hh < 2; hh++) {
                int row = bm + wm * 64 + mf * 16 + cr + hh * 8;
                if (row >= M) continue;
                float v0 = acc[mf][nf][hh * 2 + 0] + bz0;
                float v1 = acc[mf][nf][hh * 2 + 1] + bz1;
                if (GELU) {
                    v0 = 0.5f * v0 * (1.0f + erff(v0 * 0.70710678118654752f));
                    v1 = 0.5f * v1 * (1.0f + erff(v1 * 0.70710678118654752f));
                }
                if (MODE == 2) {
                    if (col < 256) {
                        __half2 hv = __halves2half2(__float2half(v0), __float2half(v1));
                        *reinterpret_cast<__half2*>(S2 + (size_t)row * 256 + col) = hv;
                    } else {
                        *reinterpret_cast<float2*>(C + (size_t)row * ldc + (col - 256)) =
                            make_float2(v0, v1);
                    }
                } else {
                    *reinterpret_cast<float2*>(C + (size_t)row * ldc + col) = make_float2(v0, v1);
                    if (MODE == 1) {
                        size_t b2 = (size_t)row * 2 * noutC;
                        __half h0 = __float2half(v0);
                        __half l0 = __float2half(v0 - __half2float(h0));
                        __half h1 = __float2half(v1);
                        __half l1 = __float2half(v1 - __half2float(h1));
                        S2[b2 + col] = h0; S2[b2 + col + 1] = h1;
                        S2[b2 + noutC + col] = l0; S2[b2 + noutC + col + 1] = l1;
                    }
                }
            }
        }
    }
}

// ---------------- pack / conversion ----------------
__global__ void pack_x2_kernel(const float* __restrict__ nf, const float* __restrict__ mem) {
    int idx = blockIdx.x * blockDim.x + threadIdx.x;
    int stride = gridDim.x * blockDim.x;
    for (int i = idx; i < N_ * 256; i += stride) {
        int n = i >> 8, j = i & 255;
        float v = (j < 128) ? nf[n * 128 + j] : mem[n * 128 + (j - 128)];
        __half hi = __float2half(v);
        __half lo = __float2half(v - __half2float(hi));
        size_t b = (size_t)n * 512;
        g_X2[b + j] = hi; g_X2[b + 256 + j] = lo;
    }
}

__global__ void pack_b_kernel(const float* __restrict__ wk_b, const float* __restrict__ wv_b,
                              const float* __restrict__ wq_b, const float* __restrict__ wq_w,
                              const float* __restrict__ te_phi) {
    int idx = blockIdx.x * blockDim.x + threadIdx.x;
    if (idx >= 2 * 768) return;
    int l = idx / 768, r = idx % 768;
    float v;
    if (r < 256)      v = wk_b[l * 256 + r];
    else if (r < 512) v = wv_b[l * 256 + (r - 256)];
    else {
        int rq = r - 512;
        v = wq_b[l * 256 + rq];
        for (int t = 0; t < 16; t++) {
            float ph = te_phi[l * 16 + t];
            float qt = (t == 0) ? ph : sinf(ph);
            v += wq_w[(size_t)(l * 256 + rq) * 272 + 256 + t] * qt;
        }
    }
    g_b[idx] = v;
}

__global__ void pack_wall_base_kernel(const float* __restrict__ wk_w, const float* __restrict__ wv_w,
                                      const float* __restrict__ wq_w) {
    int idx = blockIdx.x * blockDim.x + threadIdx.x;
    int stride = gridDim.x * blockDim.x;
    for (int i = idx; i < 2 * 1088 * 256; i += stride) {
        int l = i / (1088 * 256); int r = (i / 256) % 1088; int k = i & 255;
        size_t o = (size_t)l * 1152 * 256 + (size_t)r * 256 + k;
        if (r < 256)      g_Wall[o] = wk_w[(size_t)(l * 256 + r)       * 336 + k];
        else if (r < 512) g_Wall[o] = wv_w[(size_t)(l * 256 + (r-256)) * 336 + k];
        else if (r < 768) g_Wall[o] = wq_w[(size_t)(l * 256 + (r-512)) * 272 + k];
        // 768..1087 filled by fused kernel
    }
    for (int i = idx; i < 2 * 256 * 80; i += stride) {
        int l = i / (256 * 80); int r = (i / 80) % 256; int p = i % 80;
        g_Wev[i] = wv_w[(size_t)(l * 256 + r) * 336 + 256 + p];
    }
}

// rows 768..1087 of W_all: (WeTk blockdiag) @ Wq_h; cb bias into bias_kqp[512..832)
__global__ __launch_bounds__(256)
void pack_wall_fused_kernel(const float* __restrict__ wk_w, const float* __restrict__ wq_w) {
    __shared__ float wk_s[64];
    int b = blockIdx.x;               // 0..639
    int l = b / 320, q = b % 320;
    int hd = q / 80, p = q % 80;
    int t = threadIdx.x;
    if (t < 64) wk_s[t] = wk_w[(size_t)(l * 256 + 64 * hd + t) * 336 + 256 + p];
    __syncthreads();
    float acc = 0.f;
    for (int c = 0; c < 64; c++)
        acc += wk_s[c] * wq_w[(size_t)(l * 256 + 64 * hd + c) * 272 + t];
    g_Wall[(size_t)l * 1152 * 256 + (size_t)(768 + q) * 256 + t] = acc;
    if (t == 0) {
        float cb = 0.f;
        for (int c = 0; c < 64; c++) cb += wk_s[c] * g_b[l * 768 + 512 + 64 * hd + c];
        g_bias_kqp[l * 832 + 512 + q] = cb;
    }
}

__global__ void pack_bias_split_kernel() {
    int idx = blockIdx.x * blockDim.x + threadIdx.x;
    if (idx < 2 * 512) {
        int l = idx / 512, r = idx % 512;
        g_bias_kqp[l * 832 + r] = (r < 256) ? g_b[l * 768 + r] : g_b[l * 768 + 512 + (r - 256)];
    }
    if (idx < 2 * 256) {
        int l = idx / 256, r = idx % 256;
        g_bias_v[idx] = g_b[l * 768 + 256 + r];
    }
}

__global__ void conv_kqp_kernel() {
    int idx = blockIdx.x * blockDim.x + threadIdx.x;
    int stride = gridDim.x * blockDim.x;
    for (int i = idx; i < 2 * 832 * 512; i += stride) {
        int l = i / (832 * 512); int rem = i % (832 * 512);
        int r = rem / 512, j = rem % 512;
        int srcr = (r < 256) ? r : r + 256;
        float v = g_Wall[(size_t)l * 1152 * 256 + (size_t)srcr * 256 + (j < 256 ? j : j - 256)];
        g_Wkqp2[i] = __float2half(v);
    }
}

// combined [Wev dup | Wv dup] weights, K=704
__global__ void conv_wevv_kernel() {
    int idx = blockIdx.x * blockDim.x + threadIdx.x;
    int stride = gridDim.x * blockDim.x;
    for (int i = idx; i < 2 * 256 * 704; i += stride) {
        int l = i / (256 * 704); int rem = i % (256 * 704);
        int r = rem / 704, j = rem % 704;
        float v = 0.f;
        if (j < 80)       v = g_Wev[(size_t)l * 256 * 80 + r * 80 + j];
        else if (j < 160) v = g_Wev[(size_t)l * 256 * 80 + r * 80 + (j - 80)];
        else if (j < 192) v = 0.f;
        else if (j < 448) v = g_Wall[(size_t)l * 1152 * 256 + (size_t)(256 + r) * 256 + (j - 192)];
        else              v = g_Wall[(size_t)l * 1152 * 256 + (size_t)(256 + r) * 256 + (j - 448)];
        g_WevV2[i] = __float2half(v);
    }
}

__global__ void conv_dup_kernel(const float* __restrict__ src, int rows, int K0,
                                __half* __restrict__ dst, int KA) {
    int idx = blockIdx.x * blockDim.x + threadIdx.x;
    int stride = gridDim.x * blockDim.x;
    long total = (long)rows * KA;
    for (long i = idx; i < total; i += stride) {
        int r = (int)(i / KA); int j = (int)(i % KA);
        float v = 0.f;
        if (j < 2 * K0) v = src[(size_t)r * K0 + (j < K0 ? j : j - K0)];
        dst[i] = __float2half(v);
    }
}

// ---------------- CSR build ----------------
__global__ void csr_zero_kernel() {
    int i = blockIdx.x * blockDim.x + threadIdx.x;
    if (i < N_) g_cnt[i] = 0;
}
__global__ void csr_count_kernel(const int* __restrict__ dst) {
    int e = blockIdx.x * blockDim.x + threadIdx.x;
    if (e < E_) atomicAdd(&g_cnt[dst[e]], 1);
}
__global__ __launch_bounds__(1024)
void csr_scan_kernel() {
    __shared__ int sh[1024];
    int tid = threadIdx.x;
    const int CH = (N_ + 1023) / 1024;   // 49
    int lo = tid * CH, hi = min(lo + CH, N_);
    int s = 0;
    for (int i = lo; i < hi; i++) s += g_cnt[i];
    sh[tid] = s;
    __syncthreads();
    for (int ofs = 1; ofs < 1024; ofs <<= 1) {
        int v = (tid >= ofs) ? sh[tid - ofs] : 0;
        __syncthreads();
        sh[tid] += v;
        __syncthreads();
    }
    int run = sh[tid] - s;   // exclusive prefix
    for (int i = lo; i < hi; i++) {
        g_off[i] = run;
        run += g_cnt[i];
        g_cnt[i] = 0;        // reset as fill cursor
    }
    if (tid == 1023) g_off[N_] = sh[1023];
}
__global__ void csr_fill_kernel(const int* __restrict__ dst) {
    int e = blockIdx.x * blockDim.x + threadIdx.x;
    if (e >= E_) return;
    int d = dst[e];
    int pos = atomicAdd(&g_cnt[d], 1);
    g_eid[g_off[d] + pos] = e;
}

// ---------------- node-centric attention (gather K2/h2-hi fp16) ----------------
__global__ __launch_bounds__(256)
void node_attn_kernel(const int* __restrict__ src, const int* __restrict__ dst,
                      const float* __restrict__ ef, const float* __restrict__ et,
                      const float* __restrict__ te_w, const float* __restrict__ te_phi, int l) {
    int d = (blockIdx.x * blockDim.x + threadIdx.x) >> 5;
    int lane = threadIdx.x & 31;
    if (d >= N_) return;
    int jn = dst[d];                       // faithful h_dst[dst] quirk
    size_t jb = (size_t)jn * 576;
    int o = lane * 8;
    int hl = lane & 7;

    float q[8];
    {
        float4 q0 = *reinterpret_cast<const float4*>(g_qp + jb + o);
        float4 q1 = *reinterpret_cast<const float4*>(g_qp + jb + o + 4);
        q[0]=q0.x; q[1]=q0.y; q[2]=q0.z; q[3]=q0.w; q[4]=q1.x; q[5]=q1.y; q[6]=q1.z; q[7]=q1.w;
    }
    float Pv[10];
    {
        const float* Pr = g_qp + jb + 256 + (lane >> 3) * 80 + hl;
#pragma unroll
        for (int t = 0; t < 10; t++) Pv[t] = Pr[8 * t];
    }
    float tw = 0.f, tph = 0.f;
    if (lane < 16) { tw = te_w[l * 16 + lane]; tph = te_phi[l * 16 + lane]; }

    float aggv[8] = {};
    float am0 = 0.f, am1 = 0.f, am2 = 0.f;
    float nrm = 0.f;

    int beg = g_off[d], end = g_off[d + 1];
    for (int ii = beg; ii < end; ii++) {
        int e = g_eid[ii];
        int s = src[e];
        const float* efp = ef + (size_t)e * 64;

        // gather K' fp16 (8 halves) and h2-hi (8 halves)
        float kv[8], hv[8];
        {
            uint4 kk = *reinterpret_cast<const uint4*>(g_K2 + (size_t)s * 256 + o);
            const __half2* kp = reinterpret_cast<const __half2*>(&kk);
#pragma unroll
            for (int t = 0; t < 4; t++) {
                float2 f = __half22float2(kp[t]);
                kv[2 * t] = f.x; kv[2 * t + 1] = f.y;
            }
            uint4 hh = *reinterpret_cast<const uint4*>(g_h2 + (size_t)s * 512 + o);
            const __half2* hp = reinterpret_cast<const __half2*>(&hh);
#pragma unroll
            for (int t = 0; t < 4; t++) {
                float2 f = __half22float2(hp[t]);
                hv[2 * t] = f.x; hv[2 * t + 1] = f.y;
            }
        }

        float tv = 0.f;
        {
            float te = et[e];
            if (lane < 16) {
                float wt = -te * tw + tph;
                tv = (lane == 0) ? wt : sinf(wt);
            }
        }
        float acc = 0.f;
#pragma unroll
        for (int t = 0; t < 8; t++) acc += kv[t] * q[t];
#pragma unroll
        for (int t = 0; t < 8; t++) acc += Pv[t] * efp[hl + 8 * t];
        float t8 = __shfl_sync(0xffffffffu, tv, hl);
        float t9 = __shfl_sync(0xffffffffu, tv, hl + 8);
        acc += Pv[8] * t8 + Pv[9] * t9;

        acc += __shfl_xor_sync(0xffffffffu, acc, 1);
        acc += __shfl_xor_sync(0xffffffffu, acc, 2);
        acc += __shfl_xor_sync(0xffffffffu, acc, 4);
        float sc = fminf(5.0f, fmaxf(-5.0f, acc * 0.125f));
        float a = __expf(sc);
        float sm = a;
        sm += __shfl_xor_sync(0xffffffffu, sm, 8);
        sm += __shfl_xor_sync(0xffffffffu, sm, 16);
        float af = sm * 0.25f;

#pragma unroll
        for (int t = 0; t < 8; t++) aggv[t] += hv[t] * af;
        am0 += efp[lane] * af;
        am1 += efp[32 + lane] * af;
        if (lane < 16) am2 += tv * af;
        nrm += af;
    }

    if (lane == 0) g_nrm[d] = nrm;

    // aggc: [aggm hi80|lo80|pad32 | aggh hi256 | aggh lo256]
    __half* ac = g_aggc + (size_t)d * 704;
    {
        __half h0 = __float2half(am0);
        __half l0 = __float2half(am0 - __half2float(h0));
        ac[lane] = h0; ac[80 + lane] = l0;
        __half h1 = __float2half(am1);
        __half l1 = __float2half(am1 - __half2float(h1));
        ac[32 + lane] = h1; ac[112 + lane] = l1;
        if (lane < 16) {
            __half h2 = __float2half(am2);
            __half l2 = __float2half(am2 - __half2float(h2));
            ac[64 + lane] = h2; ac[144 + lane] = l2;
        }
        ac[160 + lane] = __float2half(0.f);
#pragma unroll
        for (int t = 0; t < 8; t++) {
            __half hh = __float2half(aggv[t]);
            __half ll = __float2half(aggv[t] - __half2float(hh));
            ac[192 + o + t] = hh;
            ac[448 + o + t] = ll;
        }
    }
}

// ---------------- node update: h = LN(h + LN((agg2 + nrm*bv)/(nrm+eps))) ----------------
__global__ __launch_bounds__(256)
void node_update_kernel(const float* __restrict__ aw, const float* __restrict__ ab,
                        const float* __restrict__ lw, const float* __restrict__ lb,
                        const float* __restrict__ bv) {
    int n = (blockIdx.x * blockDim.x + threadIdx.x) >> 5;
    int lane = threadIdx.x & 31;
    if (n >= N_) return;
    size_t base = (size_t)n * 256;
    int o = lane * 8;
    float nrm = g_nrm[n];
    float inv = 1.0f / (nrm + 1e-8f);
    float x[8];
    {
        float4 b0 = *reinterpret_cast<const float4*>(g_agg2 + base + o);
        float4 b1 = *reinterpret_cast<const float4*>(g_agg2 + base + o + 4);
        float4 v0 = *reinterpret_cast<const float4*>(bv + o);
        float4 v1 = *reinterpret_cast<const float4*>(bv + o + 4);
        x[0] = (b0.x + nrm * v0.x) * inv; x[1] = (b0.y + nrm * v0.y) * inv;
        x[2] = (b0.z + nrm * v0.z) * inv; x[3] = (b0.w + nrm * v0.w) * inv;
        x[4] = (b1.x + nrm * v1.x) * inv; x[5] = (b1.y + nrm * v1.y) * inv;
        x[6] = (b1.z + nrm * v1.z) * inv; x[7] = (b1.w + nrm * v1.w) * inv;
    }
    float s = 0.f;
#pragma unroll
    for (int i = 0; i < 8; i++) s += x[i];
#pragma unroll
    for (int m = 16; m >= 1; m >>= 1) s += __shfl_xor_sync(0xffffffffu, s, m);
    float mean = s * (1.0f / 256.0f);
    float vv = 0.f;
#pragma unroll
    for (int i = 0; i < 8; i++) { float dx = x[i] - mean; vv += dx * dx; }
#pragma unroll
    for (int m = 16; m >= 1; m >>= 1) vv += __shfl_xor_sync(0xffffffffu, vv, m);
    float is = rsqrtf(vv * (1.0f / 256.0f) + 1e-5f);
    float r[8];
#pragma unroll
    for (int i = 0; i < 8; i++) {
        float hn = (x[i] - mean) * is * aw[o + i] + ab[o + i];
        r[i] = g_h[base + o + i] + hn;
    }
    float s2 = 0.f;
#pragma unroll
    for (int i = 0; i < 8; i++) s2 += r[i];
#pragma unroll
    for (int m = 16; m >= 1; m >>= 1) s2 += __shfl_xor_sync(0xffffffffu, s2, m);
    float mean2 = s2 * (1.0f / 256.0f);
    float v2 = 0.f;
#pragma unroll
    for (int i = 0; i < 8; i++) { float dx = r[i] - mean2; v2 += dx * dx; }
#pragma unroll
    for (int m = 16; m >= 1; m >>= 1) v2 += __shfl_xor_sync(0xffffffffu, v2, m);
    float is2 = rsqrtf(v2 * (1.0f / 256.0f) + 1e-5f);
    size_t b2 = (size_t)n * 512;
#pragma unroll
    for (int i = 0; i < 8; i++) {
        float hv = (r[i] - mean2) * is2 * lw[o + i] + lb[o + i];
        g_h[base + o + i] = hv;
        __half hi = __float2half(hv);
        __half lo = __float2half(hv - __half2float(hi));
        g_h2[b2 + o + i] = hi;
        g_h2[b2 + 256 + o + i] = lo;
    }
}

// ---------------- launch ----------------
extern "C" void kernel_launch(void* const* d_in, const int* in_sizes, int n_in,
                              void* d_out, int out_size) {
    const float* node_feat  = (const float*)d_in[0];
    const float* memory     = (const float*)d_in[1];
    const int*   eidx       = (const int*)  d_in[2];
    const float* edge_feat  = (const float*)d_in[3];
    const float* edge_times = (const float*)d_in[4];
    const float* in_w       = (const float*)d_in[5];
    const float* in_b       = (const float*)d_in[6];
    const float* te_w       = (const float*)d_in[7];
    const float* te_phi     = (const float*)d_in[8];
    const float* wq_w       = (const float*)d_in[9];
    const float* wq_b       = (const float*)d_in[10];
    const float* wk_w       = (const float*)d_in[11];
    const float* wk_b       = (const float*)d_in[12];
    const float* wv_w       = (const float*)d_in[13];
    const float* wv_b       = (const float*)d_in[14];
    const float* attn_ln_w  = (const float*)d_in[15];
    const float* attn_ln_b  = (const float*)d_in[16];
    const float* ln_w       = (const float*)d_in[17];
    const float* ln_b       = (const float*)d_in[18];
    const float* out_w      = (const float*)d_in[19];
    const float* out_b      = (const float*)d_in[20];
    const int* src = eidx;
    const int* dst = eidx + E_;
    float* out = (float*)d_out;

    float *ph, *pQP, *pAgg2, *pWev, *pBiasKQP, *pBiasV;
    __half *pX2, *ph2, *pK2, *pAggc, *pWkqp2, *pWevV2, *pWin2, *pWout2;
    cudaGetSymbolAddress((void**)&ph,       g_h);
    cudaGetSymbolAddress((void**)&pQP,      g_qp);
    cudaGetSymbolAddress((void**)&pAgg2,    g_agg2);
    cudaGetSymbolAddress((void**)&pWev,     g_Wev);
    cudaGetSymbolAddress((void**)&pBiasKQP, g_bias_kqp);
    cudaGetSymbolAddress((void**)&pBiasV,   g_bias_v);
    cudaGetSymbolAddress((void**)&pX2,      g_X2);
    cudaGetSymbolAddress((void**)&ph2,      g_h2);
    cudaGetSymbolAddress((void**)&pK2,      g_K2);
    cudaGetSymbolAddress((void**)&pAggc,    g_aggc);
    cudaGetSymbolAddress((void**)&pWkqp2,   g_Wkqp2);
    cudaGetSymbolAddress((void**)&pWevV2,   g_WevV2);
    cudaGetSymbolAddress((void**)&pWin2,    g_Win2);
    cudaGetSymbolAddress((void**)&pWout2,   g_Wout2);

    cudaFuncSetAttribute(mma_gemm<0, false>, cudaFuncAttributeMaxDynamicSharedMemorySize, GSMEM_BYTES);
    cudaFuncSetAttribute(mma_gemm<1, false>, cudaFuncAttributeMaxDynamicSharedMemorySize, GSMEM_BYTES);
    cudaFuncSetAttribute(mma_gemm<2, false>, cudaFuncAttributeMaxDynamicSharedMemorySize, GSMEM_BYTES);
    cudaFuncSetAttribute(mma_gemm<0, true>,  cudaFuncAttributeMaxDynamicSharedMemorySize, GSMEM_BYTES);

    const int GX = (N_ + 127) / 128;  // 391

    pack_x2_kernel<<<4096, 256>>>(node_feat, memory);
    pack_b_kernel<<<6, 256>>>(wk_b, wv_b, wq_b, wq_w, te_phi);
    pack_wall_base_kernel<<<2304, 256>>>(wk_w, wv_w, wq_w);
    pack_wall_fused_kernel<<<640, 256>>>(wk_w, wq_w);
    pack_bias_split_kernel<<<4, 256>>>();
    conv_kqp_kernel<<<1664, 256>>>();
    conv_wevv_kernel<<<704, 256>>>();
    conv_dup_kernel<<<512, 256>>>((const float*)in_w, 256, 256, pWin2, 512);
    conv_dup_kernel<<<128, 256>>>((const float*)out_w, 64, 256, pWout2, 512);

    // CSR build (topology is layer-independent)
    csr_zero_kernel<<<(N_ + 255) / 256, 256>>>();
    csr_count_kernel<<<(E_ + 255) / 256, 256>>>(dst);
    csr_scan_kernel<<<1, 1024>>>();
    csr_fill_kernel<<<(E_ + 255) / 256, 256>>>(dst);

    // h = X @ in_w^T + in_b (also emits h2 split)
    mma_gemm<1, false><<<dim3(GX, 2), 256, GSMEM_BYTES>>>(
        pX2, 512, 512, pWin2, 512, 256, in_b, ph, 256, N_, 256, ph2);

    for (int l = 0; l < 2; l++) {
        // [K'(fp16)|Q'|P] = h @ Wkqp^T + [bk|bq_eff|cb]
        mma_gemm<2, false><<<dim3(GX, 7), 256, GSMEM_BYTES>>>(
            ph2, 512, 512, pWkqp2 + (size_t)l * 832 * 512, 512, 832,
            pBiasKQP + l * 832, pQP, 576, N_, 832, pK2);
        node_attn_kernel<<<6250, 256>>>(src, dst, edge_feat, edge_times, te_w, te_phi, l);
        // agg2 = [aggm|aggh] @ [Wev|Wv]^T   (K=704)
        mma_gemm<0, false><<<dim3(GX, 2), 256, GSMEM_BYTES>>>(
            pAggc, 704, 704, pWevV2 + (size_t)l * 256 * 704, 704, 256,
            nullptr, pAgg2, 256, N_, 256, nullptr);
        node_update_kernel<<<6250, 256>>>(attn_ln_w + l * 256, attn_ln_b + l * 256,
                                          ln_w + l * 256, ln_b + l * 256,
                                          pBiasV + l * 256);
    }

    // out = gelu(h @ out_w^T + out_b)
    mma_gemm<0, true><<<dim3(GX, 1), 256, GSMEM_BYTES>>>(
        ph2, 512, 512, pWout2, 512, 64, out_b, out, 64, N_, 64, nullptr);
}

// round 16
// speedup vs baseline: 1.0002x; 1.0002x over previous
#include <cuda_runtime.h>
#include <cuda_fp16.h>
#include <math.h>
#include <stdint.h>

static constexpr int N_ = 50000;
static constexpr int E_ = 200000;

// ---------------- scratch ----------------
__device__ __half  g_X2   [(size_t)N_ * 512];   // [hi|lo] fp16 split of [nf|mem]
__device__ float   g_h    [(size_t)N_ * 256];
__device__ __half  g_h2   [(size_t)N_ * 512];   // [hi|lo] split of h
__device__ float   g_qp   [(size_t)N_ * 576];   // [Q'(256)|P(320)] per node (fp32)
__device__ __half  g_K2   [(size_t)N_ * 256];   // K' fp16 compact (bias folded)
__device__ __half  g_V2   [(size_t)N_ * 256];   // V' fp16 compact (bias folded)
__device__ float   g_agg  [(size_t)N_ * 256];
__device__ float   g_agg2 [(size_t)N_ * 256];
__device__ __half  g_aggm2[(size_t)N_ * 192];   // [hi80|lo80|pad32] fp16 split of aggm
__device__ float   g_nrm  [N_];
__device__ float   g_Wall [2 * 1152 * 256];     // fp32 [Wk;Wv;Wq;Wfused]
__device__ __half  g_Wkqp2[2 * 832 * 512];      // dup fp16 [Wk;Wq;Wfused]
__device__ __half  g_Wv2h [2 * 256 * 256];      // single fp16 Wv
__device__ float   g_bias_kqp[2 * 832];         // [bk|bq_eff|cb]
__device__ float   g_bias_v  [2 * 256];         // bv
__device__ __half  g_Win2 [256 * 512];
__device__ float   g_Wev  [2 * 256 * 80];
__device__ __half  g_Wev2 [2 * 256 * 192];
__device__ __half  g_Wout2[64 * 512];
__device__ float   g_b    [2 * 768];            // [bk|bv|bq_eff]
// CSR
__device__ int g_off [N_ + 1];
__device__ int g_cnt [N_];
__device__ int g_eid [E_];

// ---------------- ptx helpers (family-safe, sm_80 baseline) ----------------
__device__ __forceinline__ uint32_t smem_u32(const void* p) {
    uint32_t a;
    asm("{ .reg .u64 t; cvta.to.shared.u64 t, %1; cvt.u32.u64 %0, t; }" : "=r"(a) : "l"(p));
    return a;
}
__device__ __forceinline__ void cp16(uint32_t dst, const void* src, int pred) {
    asm volatile(
        "{\n\t.reg .pred p;\n\t"
        "setp.ne.u32 p, %2, 0;\n\t"
        "@p cp.async.ca.shared.global [%0], [%1], 16;\n\t"
        "@!p cp.async.ca.shared.global [%0], [%1], 16, 0;\n\t}"
        :: "r"(dst), "l"(src), "r"(pred) : "memory");
}
__device__ __forceinline__ void cp_commit() {
    asm volatile("cp.async.commit_group;" ::: "memory");
}
__device__ __forceinline__ void ldm4(uint32_t* r, uint32_t addr) {
    asm volatile("ldmatrix.sync.aligned.m8n8.x4.shared.b16 {%0,%1,%2,%3}, [%4];"
                 : "=r"(r[0]), "=r"(r[1]), "=r"(r[2]), "=r"(r[3]) : "r"(addr));
}
__device__ __forceinline__ void mma16816(float* c, const uint32_t* a, const uint32_t* b) {
    asm volatile(
        "mma.sync.aligned.m16n8k16.row.col.f32.f16.f16.f32 "
        "{%0,%1,%2,%3},{%4,%5,%6,%7},{%8,%9},{%0,%1,%2,%3};"
        : "+f"(c[0]), "+f"(c[1]), "+f"(c[2]), "+f"(c[3])
        : "r"(a[0]), "r"(a[1]), "r"(a[2]), "r"(a[3]), "r"(b[0]), "r"(b[1]));
}

// ---------------- mma.sync GEMM (double-buffered, K chunks of 64) ----------------
// MODE 0: plain fp32 C.  MODE 1: fp32 C + fp16 [hi|lo] split into S2.
// MODE 2 (KQP): col<256 -> fp16 into S2 (K'); col>=256 -> fp32 C at col-256 (Q'|P).
// MODE 3: fp16 compact into S2 only (V').
static constexpr int GSAS = 72;
static constexpr int GSEG = 128 * GSAS;
static constexpr int GSMEM_BYTES = 4 * GSEG * 2;  // 73728

template <int MODE, bool GELU>
__global__ __launch_bounds__(256)
void mma_gemm(const __half* __restrict__ A2, int lda, int klen,
              const __half* __restrict__ W2, int ldw, int noutW,
              const float* __restrict__ bias,
              float* __restrict__ C, int ldc, int M, int noutC,
              __half* __restrict__ S2) {
    extern __shared__ __align__(16) __half smem[];
    int tid = threadIdx.x, lane = tid & 31, wid = tid >> 5;
    int wm = wid & 1, wn = wid >> 1;
    int bm = blockIdx.x * 128, bn = blockIdx.y * 128;
    int NC = klen >> 6;
    uint32_t sU = smem_u32(smem);

    int arow = (lane & 7) + ((lane >> 3) & 1) * 8;
    int acol = ((lane >> 4) & 1) * 8;
    int bco  = ((lane >> 4) & 1) * 8 + (lane & 7);
    int bko  = ((lane >> 3) & 1) * 8;

    float acc[4][4][4] = {};

#define LOADC(c, buf)                                                                    \
    {                                                                                    \
        int _c64 = (c) * 64;                                                             \
        uint32_t _ab = sU + (buf) * (2 * GSEG * 2);                                      \
        uint32_t _bb = _ab + GSEG * 2;                                                   \
        _Pragma("unroll")                                                                \
        for (int _k = 0; _k < 4; _k++) {                                                 \
            int _id = tid + _k * 256;                                                    \
            int _r = _id >> 3, _cg = (_id & 7) * 8;                                      \
            uint32_t _so = (uint32_t)(_r * GSAS + _cg) * 2;                              \
            int _gr = bm + _r; int _pa = _gr < M; int _ga = _pa ? _gr : 0;               \
            cp16(_ab + _so, A2 + (size_t)_ga * lda + _c64 + _cg, _pa);                   \
            int _wr = bn + _r; int _pb = _wr < noutW; int _wa = _pb ? _wr : 0;           \
            cp16(_bb + _so, W2 + (size_t)_wa * ldw + _c64 + _cg, _pb);                   \
        }                                                                                \
        cp_commit();                                                                     \
    }

    LOADC(0, 0);
    for (int c = 0; c < NC; c++) {
        if (c + 1 < NC) {
            LOADC(c + 1, (c + 1) & 1);
            asm volatile("cp.async.wait_group 1;" ::: "memory");
        } else {
            asm volatile("cp.async.wait_group 0;" ::: "memory");
        }
        __syncthreads();
        uint32_t sAb = sU + (c & 1) * (2 * GSEG * 2);
        uint32_t sBb = sAb + GSEG * 2;
#pragma unroll
        for (int ks = 0; ks < 4; ks++) {
            uint32_t af[4][4];
#pragma unroll
            for (int mf = 0; mf < 4; mf++)
                ldm4(af[mf], sAb + (uint32_t)((wm * 64 + mf * 16 + arow) * GSAS + ks * 16 + acol) * 2);
            uint32_t bf[4][2];
#pragma unroll
            for (int p = 0; p < 2; p++) {
                uint32_t r4[4];
                ldm4(r4, sBb + (uint32_t)((wn * 32 + p * 16 + bco) * GSAS + ks * 16 + bko) * 2);
                bf[2 * p][0] = r4[0]; bf[2 * p][1] = r4[1];
                bf[2 * p + 1][0] = r4[2]; bf[2 * p + 1][1] = r4[3];
            }
#pragma unroll
            for (int mf = 0; mf < 4; mf++)
#pragma unroll
                for (int nf = 0; nf < 4; nf++)
                    mma16816(acc[mf][nf], af[mf], bf[nf]);
        }
        __syncthreads();
    }
#undef LOADC

    int cr = lane >> 2, cc = (lane & 3) * 2;
#pragma unroll
    for (int mf = 0; mf < 4; mf++) {
#pragma unroll
        for (int nf = 0; nf < 4; nf++) {
            int col = bn + wn * 32 + nf * 8 + cc;
            if (col >= noutC) continue;
            float bz0 = bias ? bias[col] : 0.f;
            float bz1 = bias ? bias[col + 1] : 0.f;
#pragma unroll
            for (int hh = 0; hh < 2; hh++) {
                int row = bm + wm * 64 + mf * 16 + cr + hh * 8;
                if (row >= M) continue;
                float v0 = acc[mf][nf][hh * 2 + 0] + bz0;
                float v1 = acc[mf][nf][hh * 2 + 1] + bz1;
                if (GELU) {
                    v0 = 0.5f * v0 * (1.0f + erff(v0 * 0.70710678118654752f));
                    v1 = 0.5f * v1 * (1.0f + erff(v1 * 0.70710678118654752f));
                }
                if (MODE == 2) {
                    if (col < 256) {
                        __half2 hv = __halves2half2(__float2half(v0), __float2half(v1));
                        *reinterpret_cast<__half2*>(S2 + (size_t)row * 256 + col) = hv;
                    } else {
                        *reinterpret_cast<float2*>(C + (size_t)row * ldc + (col - 256)) =
                            make_float2(v0, v1);
                    }
                } else if (MODE == 3) {
                    __half2 hv = __halves2half2(__float2half(v0), __float2half(v1));
                    *reinterpret_cast<__half2*>(S2 + (size_t)row * 256 + col) = hv;
                } else {
                    *reinterpret_cast<float2*>(C + (size_t)row * ldc + col) = make_float2(v0, v1);
                    if (MODE == 1) {
                        size_t b2 = (size_t)row * 2 * noutC;
                        __half h0 = __float2half(v0);
                        __half l0 = __float2half(v0 - __half2float(h0));
                        __half h1 = __float2half(v1);
                        __half l1 = __float2half(v1 - __half2float(h1));
                        S2[b2 + col] = h0; S2[b2 + col + 1] = h1;
                        S2[b2 + noutC + col] = l0; S2[b2 + noutC + col + 1] = l1;
                    }
                }
            }
        }
    }
}

// ---------------- pack / conversion ----------------
__global__ void pack_x2_kernel(const float* __restrict__ nf, const float* __restrict__ mem) {
    int idx = blockIdx.x * blockDim.x + threadIdx.x;
    int stride = gridDim.x * blockDim.x;
    for (int i = idx; i < N_ * 256; i += stride) {
        int n = i >> 8, j = i & 255;
        float v = (j < 128) ? nf[n * 128 + j] : mem[n * 128 + (j - 128)];
        __half hi = __float2half(v);
        __half lo = __float2half(v - __half2float(hi));
        size_t b = (size_t)n * 512;
        g_X2[b + j] = hi; g_X2[b + 256 + j] = lo;
    }
}

__global__ void pack_b_kernel(const float* __restrict__ wk_b, const float* __restrict__ wv_b,
                              const float* __restrict__ wq_b, const float* __restrict__ wq_w,
                              const float* __restrict__ te_phi) {
    int idx = blockIdx.x * blockDim.x + threadIdx.x;
    if (idx >= 2 * 768) return;
    int l = idx / 768, r = idx % 768;
    float v;
    if (r < 256)      v = wk_b[l * 256 + r];
    else if (r < 512) v = wv_b[l * 256 + (r - 256)];
    else {
        int rq = r - 512;
        v = wq_b[l * 256 + rq];
        for (int t = 0; t < 16; t++) {
            float ph = te_phi[l * 16 + t];
            float qt = (t == 0) ? ph : sinf(ph);
            v += wq_w[(size_t)(l * 256 + rq) * 272 + 256 + t] * qt;
        }
    }
    g_b[idx] = v;
}

__global__ void pack_wall_base_kernel(const float* __restrict__ wk_w, const float* __restrict__ wv_w,
                                      const float* __restrict__ wq_w) {
    int idx = blockIdx.x * blockDim.x + threadIdx.x;
    int stride = gridDim.x * blockDim.x;
    for (int i = idx; i < 2 * 1088 * 256; i += stride) {
        int l = i / (1088 * 256); int r = (i / 256) % 1088; int k = i & 255;
        size_t o = (size_t)l * 1152 * 256 + (size_t)r * 256 + k;
        if (r < 256)      g_Wall[o] = wk_w[(size_t)(l * 256 + r)       * 336 + k];
        else if (r < 512) g_Wall[o] = wv_w[(size_t)(l * 256 + (r-256)) * 336 + k];
        else if (r < 768) g_Wall[o] = wq_w[(size_t)(l * 256 + (r-512)) * 272 + k];
    }
    for (int i = idx; i < 2 * 256 * 80; i += stride) {
        int l = i / (256 * 80); int r = (i / 80) % 256; int p = i % 80;
        g_Wev[i] = wv_w[(size_t)(l * 256 + r) * 336 + 256 + p];
    }
}

__global__ __launch_bounds__(256)
void pack_wall_fused_kernel(const float* __restrict__ wk_w, const float* __restrict__ wq_w) {
    __shared__ float wk_s[64];
    int b = blockIdx.x;               // 0..639
    int l = b / 320, q = b % 320;
    int hd = q / 80, p = q % 80;
    int t = threadIdx.x;
    if (t < 64) wk_s[t] = wk_w[(size_t)(l * 256 + 64 * hd + t) * 336 + 256 + p];
    __syncthreads();
    float acc = 0.f;
    for (int c = 0; c < 64; c++)
        acc += wk_s[c] * wq_w[(size_t)(l * 256 + 64 * hd + c) * 272 + t];
    g_Wall[(size_t)l * 1152 * 256 + (size_t)(768 + q) * 256 + t] = acc;
    if (t == 0) {
        float cb = 0.f;
        for (int c = 0; c < 64; c++) cb += wk_s[c] * g_b[l * 768 + 512 + 64 * hd + c];
        g_bias_kqp[l * 832 + 512 + q] = cb;
    }
}

__global__ void pack_bias_split_kernel() {
    int idx = blockIdx.x * blockDim.x + threadIdx.x;
    if (idx < 2 * 512) {
        int l = idx / 512, r = idx % 512;
        g_bias_kqp[l * 832 + r] = (r < 256) ? g_b[l * 768 + r] : g_b[l * 768 + 512 + (r - 256)];
    }
    if (idx < 2 * 256) {
        int l = idx / 256, r = idx % 256;
        g_bias_v[idx] = g_b[l * 768 + 256 + r];
    }
}

__global__ void conv_kqp_kernel() {
    int idx = blockIdx.x * blockDim.x + threadIdx.x;
    int stride = gridDim.x * blockDim.x;
    for (int i = idx; i < 2 * 832 * 512; i += stride) {
        int l = i / (832 * 512); int rem = i % (832 * 512);
        int r = rem / 512, j = rem % 512;
        int srcr = (r < 256) ? r : r + 256;
        float v = g_Wall[(size_t)l * 1152 * 256 + (size_t)srcr * 256 + (j < 256 ? j : j - 256)];
        g_Wkqp2[i] = __float2half(v);
    }
}

__global__ void conv_v_kernel() {
    int idx = blockIdx.x * blockDim.x + threadIdx.x;
    int stride = gridDim.x * blockDim.x;
    for (int i = idx; i < 2 * 256 * 256; i += stride) {
        int l = i / (256 * 256); int rem = i % (256 * 256);
        int r = rem / 256, j = rem % 256;
        g_Wv2h[i] = __float2half(g_Wall[(size_t)l * 1152 * 256 + (size_t)(256 + r) * 256 + j]);
    }
}

__global__ void conv_dup_kernel(const float* __restrict__ src, int rows, int K0,
                                __half* __restrict__ dst, int KA) {
    int idx = blockIdx.x * blockDim.x + threadIdx.x;
    int stride = gridDim.x * blockDim.x;
    long total = (long)rows * KA;
    for (long i = idx; i < total; i += stride) {
        int r = (int)(i / KA); int j = (int)(i % KA);
        float v = 0.f;
        if (j < 2 * K0) v = src[(size_t)r * K0 + (j < K0 ? j : j - K0)];
        dst[i] = __float2half(v);
    }
}

// ---------------- CSR build ----------------
__global__ void csr_zero_kernel() {
    int i = blockIdx.x * blockDim.x + threadIdx.x;
    if (i < N_) g_cnt[i] = 0;
}
__global__ void csr_count_kernel(const int* __restrict__ dst) {
    int e = blockIdx.x * blockDim.x + threadIdx.x;
    if (e < E_) atomicAdd(&g_cnt[dst[e]], 1);
}
__global__ __launch_bounds__(1024)
void csr_scan_kernel() {
    __shared__ int sh[1024];
    int tid = threadIdx.x;
    const int CH = (N_ + 1023) / 1024;   // 49
    int lo = tid * CH, hi = min(lo + CH, N_);
    int s = 0;
    for (int i = lo; i < hi; i++) s += g_cnt[i];
    sh[tid] = s;
    __syncthreads();
    for (int ofs = 1; ofs < 1024; ofs <<= 1) {
        int v = (tid >= ofs) ? sh[tid - ofs] : 0;
        __syncthreads();
        sh[tid] += v;
        __syncthreads();
    }
    int run = sh[tid] - s;   // exclusive prefix
    for (int i = lo; i < hi; i++) {
        g_off[i] = run;
        run += g_cnt[i];
        g_cnt[i] = 0;        // reset as fill cursor
    }
    if (tid == 1023) g_off[N_] = sh[1023];
}
__global__ void csr_fill_kernel(const int* __restrict__ dst) {
    int e = blockIdx.x * blockDim.x + threadIdx.x;
    if (e >= E_) return;
    int d = dst[e];
    int pos = atomicAdd(&g_cnt[d], 1);
    g_eid[g_off[d] + pos] = e;
}

// ---------------- node-centric attention (fp16 K'/V' gathers) ----------------
__global__ __launch_bounds__(256)
void node_attn_kernel(const int* __restrict__ src, const int* __restrict__ dst,
                      const float* __restrict__ ef, const float* __restrict__ et,
                      const float* __restrict__ te_w, const float* __restrict__ te_phi, int l) {
    int d = (blockIdx.x * blockDim.x + threadIdx.x) >> 5;
    int lane = threadIdx.x & 31;
    if (d >= N_) return;
    int jn = dst[d];                       // faithful h_dst[dst] quirk
    size_t jb = (size_t)jn * 576;
    int o = lane * 8;
    int hl = lane & 7;

    float q[8];
    {
        float4 q0 = *reinterpret_cast<const float4*>(g_qp + jb + o);
        float4 q1 = *reinterpret_cast<const float4*>(g_qp + jb + o + 4);
        q[0]=q0.x; q[1]=q0.y; q[2]=q0.z; q[3]=q0.w; q[4]=q1.x; q[5]=q1.y; q[6]=q1.z; q[7]=q1.w;
    }
    float Pv[10];
    {
        const float* Pr = g_qp + jb + 256 + (lane >> 3) * 80 + hl;
#pragma unroll
        for (int t = 0; t < 10; t++) Pv[t] = Pr[8 * t];
    }
    float tw = 0.f, tph = 0.f;
    if (lane < 16) { tw = te_w[l * 16 + lane]; tph = te_phi[l * 16 + lane]; }

    float aggv[8] = {};
    float am0 = 0.f, am1 = 0.f, am2 = 0.f;
    float nrm = 0.f;

    int beg = g_off[d], end = g_off[d + 1];
    for (int ii = beg; ii < end; ii++) {
        int e = g_eid[ii];
        int s = src[e];
        const float* efp = ef + (size_t)e * 64;

        float kv[8], hv[8];
        {
            uint4 kk = *reinterpret_cast<const uint4*>(g_K2 + (size_t)s * 256 + o);
            const __half2* kp = reinterpret_cast<const __half2*>(&kk);
#pragma unroll
            for (int t = 0; t < 4; t++) {
                float2 f = __half22float2(kp[t]);
                kv[2 * t] = f.x; kv[2 * t + 1] = f.y;
            }
            uint4 vv4 = *reinterpret_cast<const uint4*>(g_V2 + (size_t)s * 256 + o);
            const __half2* vp = reinterpret_cast<const __half2*>(&vv4);
#pragma unroll
            for (int t = 0; t < 4; t++) {
                float2 f = __half22float2(vp[t]);
                hv[2 * t] = f.x; hv[2 * t + 1] = f.y;
            }
        }

        float tv = 0.f;
        {
            float te = et[e];
            if (lane < 16) {
                float wt = -te * tw + tph;
                tv = (lane == 0) ? wt : sinf(wt);
            }
        }
        float acc = 0.f;
#pragma unroll
        for (int t = 0; t < 8; t++) acc += kv[t] * q[t];
#pragma unroll
        for (int t = 0; t < 8; t++) acc += Pv[t] * efp[hl + 8 * t];
        float t8 = __shfl_sync(0xffffffffu, tv, hl);
        float t9 = __shfl_sync(0xffffffffu, tv, hl + 8);
        acc += Pv[8] * t8 + Pv[9] * t9;

        acc += __shfl_xor_sync(0xffffffffu, acc, 1);
        acc += __shfl_xor_sync(0xffffffffu, acc, 2);
        acc += __shfl_xor_sync(0xffffffffu, acc, 4);
        float sc = fminf(5.0f, fmaxf(-5.0f, acc * 0.125f));
        float a = __expf(sc);
        float sm = a;
        sm += __shfl_xor_sync(0xffffffffu, sm, 8);
        sm += __shfl_xor_sync(0xffffffffu, sm, 16);
        float af = sm * 0.25f;

#pragma unroll
        for (int t = 0; t < 8; t++) aggv[t] += hv[t] * af;
        am0 += efp[lane] * af;
        am1 += efp[32 + lane] * af;
        if (lane < 16) am2 += tv * af;
        nrm += af;
    }

    size_t base = (size_t)d * 256;
    *reinterpret_cast<float4*>(g_agg + base + o)     = make_float4(aggv[0], aggv[1], aggv[2], aggv[3]);
    *reinterpret_cast<float4*>(g_agg + base + o + 4) = make_float4(aggv[4], aggv[5], aggv[6], aggv[7]);
    if (lane == 0) g_nrm[d] = nrm;

    // aggm2: [hi(80) | lo(80) | pad(32, stays zero)]
    __half* am = g_aggm2 + (size_t)d * 192;
    {
        __half h0 = __float2half(am0);
        __half l0 = __float2half(am0 - __half2float(h0));
        am[lane] = h0; am[80 + lane] = l0;
        __half h1 = __float2half(am1);
        __half l1 = __float2half(am1 - __half2float(h1));
        am[32 + lane] = h1; am[112 + lane] = l1;
        if (lane < 16) {
            __half h2 = __float2half(am2);
            __half l2 = __float2half(am2 - __half2float(h2));
            am[64 + lane] = h2; am[144 + lane] = l2;
        }
    }
}

// ---------------- node update: h = LN(h + LN((agg+agg2)/(nrm+eps))); writes h and h2 ----------------
__global__ __launch_bounds__(256)
void node_update_kernel(const float* __restrict__ aw, const float* __restrict__ ab,
                        const float* __restrict__ lw, const float* __restrict__ lb) {
    int n = (blockIdx.x * blockDim.x + threadIdx.x) >> 5;
    int lane = threadIdx.x & 31;
    if (n >= N_) return;
    size_t base = (size_t)n * 256;
    int o = lane * 8;
    float inv = 1.0f / (g_nrm[n] + 1e-8f);
    float x[8];
    {
        float4 a0 = *reinterpret_cast<const float4*>(g_agg  + base + o);
        float4 a1 = *reinterpret_cast<const float4*>(g_agg  + base + o + 4);
        float4 b0 = *reinterpret_cast<const float4*>(g_agg2 + base + o);
        float4 b1 = *reinterpret_cast<const float4*>(g_agg2 + base + o + 4);
        x[0] = (a0.x + b0.x) * inv; x[1] = (a0.y + b0.y) * inv;
        x[2] = (a0.z + b0.z) * inv; x[3] = (a0.w + b0.w) * inv;
        x[4] = (a1.x + b1.x) * inv; x[5] = (a1.y + b1.y) * inv;
        x[6] = (a1.z + b1.z) * inv; x[7] = (a1.w + b1.w) * inv;
    }
    float s = 0.f;
#pragma unroll
    for (int i = 0; i < 8; i++) s += x[i];
#pragma unroll
    for (int m = 16; m >= 1; m >>= 1) s += __shfl_xor_sync(0xffffffffu, s, m);
    float mean = s * (1.0f / 256.0f);
    float vv = 0.f;
#pragma unroll
    for (int i = 0; i < 8; i++) { float dx = x[i] - mean; vv += dx * dx; }
#pragma unroll
    for (int m = 16; m >= 1; m >>= 1) vv += __shfl_xor_sync(0xffffffffu, vv, m);
    float is = rsqrtf(vv * (1.0f / 256.0f) + 1e-5f);
    float r[8];
#pragma unroll
    for (int i = 0; i < 8; i++) {
        float hn = (x[i] - mean) * is * aw[o + i] + ab[o + i];
        r[i] = g_h[base + o + i] + hn;
    }
    float s2 = 0.f;
#pragma unroll
    for (int i = 0; i < 8; i++) s2 += r[i];
#pragma unroll
    for (int m = 16; m >= 1; m >>= 1) s2 += __shfl_xor_sync(0xffffffffu, s2, m);
    float mean2 = s2 * (1.0f / 256.0f);
    float v2 = 0.f;
#pragma unroll
    for (int i = 0; i < 8; i++) { float dx = r[i] - mean2; v2 += dx * dx; }
#pragma unroll
    for (int m = 16; m >= 1; m >>= 1) v2 += __shfl_xor_sync(0xffffffffu, v2, m);
    float is2 = rsqrtf(v2 * (1.0f / 256.0f) + 1e-5f);
    size_t b2 = (size_t)n * 512;
#pragma unroll
    for (int i = 0; i < 8; i++) {
        float hv = (r[i] - mean2) * is2 * lw[o + i] + lb[o + i];
        g_h[base + o + i] = hv;
        __half hi = __float2half(hv);
        __half lo = __float2half(hv - __half2float(hi));
        g_h2[b2 + o + i] = hi;
        g_h2[b2 + 256 + o + i] = lo;
    }
}

// ---------------- launch ----------------
extern "C" void kernel_launch(void* const* d_in, const int* in_sizes, int n_in,
                              void* d_out, int out_size) {
    const float* node_feat  = (const float*)d_in[0];
    const float* memory     = (const float*)d_in[1];
    const int*   eidx       = (const int*)  d_in[2];
    const float* edge_feat  = (const float*)d_in[3];
    const float* edge_times = (const float*)d_in[4];
    const float* in_w       = (const float*)d_in[5];
    const float* in_b       = (const float*)d_in[6];
    const float* te_w       = (const float*)d_in[7];
    const float* te_phi     = (const float*)d_in[8];
    const float* wq_w       = (const float*)d_in[9];
    const float* wq_b       = (const float*)d_in[10];
    const float* wk_w       = (const float*)d_in[11];
    const float* wk_b       = (const float*)d_in[12];
    const float* wv_w       = (const float*)d_in[13];
    const float* wv_b       = (const float*)d_in[14];
    const float* attn_ln_w  = (const float*)d_in[15];
    const float* attn_ln_b  = (const float*)d_in[16];
    const float* ln_w       = (const float*)d_in[17];
    const float* ln_b       = (const float*)d_in[18];
    const float* out_w      = (const float*)d_in[19];
    const float* out_b      = (const float*)d_in[20];
    const int* src = eidx;
    const int* dst = eidx + E_;
    float* out = (float*)d_out;

    float *ph, *pQP, *pAgg2, *pWev, *pBiasKQP, *pBiasV;
    __half *pX2, *ph2, *pK2, *pV2, *pAggm2, *pWkqp2, *pWv2h, *pWin2, *pWev2, *pWout2;
    cudaGetSymbolAddress((void**)&ph,       g_h);
    cudaGetSymbolAddress((void**)&pQP,      g_qp);
    cudaGetSymbolAddress((void**)&pAgg2,    g_agg2);
    cudaGetSymbolAddress((void**)&pWev,     g_Wev);
    cudaGetSymbolAddress((void**)&pBiasKQP, g_bias_kqp);
    cudaGetSymbolAddress((void**)&pBiasV,   g_bias_v);
    cudaGetSymbolAddress((void**)&pX2,      g_X2);
    cudaGetSymbolAddress((void**)&ph2,      g_h2);
    cudaGetSymbolAddress((void**)&pK2,      g_K2);
    cudaGetSymbolAddress((void**)&pV2,      g_V2);
    cudaGetSymbolAddress((void**)&pAggm2,   g_aggm2);
    cudaGetSymbolAddress((void**)&pWkqp2,   g_Wkqp2);
    cudaGetSymbolAddress((void**)&pWv2h,    g_Wv2h);
    cudaGetSymbolAddress((void**)&pWin2,    g_Win2);
    cudaGetSymbolAddress((void**)&pWev2,    g_Wev2);
    cudaGetSymbolAddress((void**)&pWout2,   g_Wout2);

    cudaFuncSetAttribute(mma_gemm<0, false>, cudaFuncAttributeMaxDynamicSharedMemorySize, GSMEM_BYTES);
    cudaFuncSetAttribute(mma_gemm<1, false>, cudaFuncAttributeMaxDynamicSharedMemorySize, GSMEM_BYTES);
    cudaFuncSetAttribute(mma_gemm<2, false>, cudaFuncAttributeMaxDynamicSharedMemorySize, GSMEM_BYTES);
    cudaFuncSetAttribute(mma_gemm<3, false>, cudaFuncAttributeMaxDynamicSharedMemorySize, GSMEM_BYTES);
    cudaFuncSetAttribute(mma_gemm<0, true>,  cudaFuncAttributeMaxDynamicSharedMemorySize, GSMEM_BYTES);

    const int GX = (N_ + 127) / 128;  // 391

    pack_x2_kernel<<<4096, 256>>>(node_feat, memory);
    pack_b_kernel<<<6, 256>>>(wk_b, wv_b, wq_b, wq_w, te_phi);
    pack_wall_base_kernel<<<2304, 256>>>(wk_w, wv_w, wq_w);
    pack_wall_fused_kernel<<<640, 256>>>(wk_w, wq_w);
    pack_bias_split_kernel<<<4, 256>>>();
    conv_kqp_kernel<<<1664, 256>>>();
    conv_v_kernel<<<512, 256>>>();
    conv_dup_kernel<<<512, 256>>>((const float*)in_w, 256, 256, pWin2, 512);
    conv_dup_kernel<<<128, 256>>>((const float*)out_w, 64, 256, pWout2, 512);
    conv_dup_kernel<<<384, 256>>>(pWev, 2 * 256, 80, pWev2, 192);

    // CSR build (topology is layer-independent)
    csr_zero_kernel<<<(N_ + 255) / 256, 256>>>();
    csr_count_kernel<<<(E_ + 255) / 256, 256>>>(dst);
    csr_scan_kernel<<<1, 1024>>>();
    csr_fill_kernel<<<(E_ + 255) / 256, 256>>>(dst);

    // h = X @ in_w^T + in_b (also emits h2 split)
    mma_gemm<1, false><<<dim3(GX, 2), 256, GSMEM_BYTES>>>(
        pX2, 512, 512, pWin2, 512, 256, in_b, ph, 256, N_, 256, ph2);

    for (int l = 0; l < 2; l++) {
        // [K'(fp16)|Q'|P] = h @ Wkqp^T + [bk|bq_eff|cb]
        mma_gemm<2, false><<<dim3(GX, 7), 256, GSMEM_BYTES>>>(
            ph2, 512, 512, pWkqp2 + (size_t)l * 832 * 512, 512, 832,
            pBiasKQP + l * 832, pQP, 576, N_, 832, pK2);
        // V'(fp16) = h_hi @ Wv^T + bv   (hi-only, K=256)
        mma_gemm<3, false><<<dim3(GX, 2), 256, GSMEM_BYTES>>>(
            ph2, 512, 256, pWv2h + (size_t)l * 256 * 256, 256, 256,
            pBiasV + l * 256, nullptr, 0, N_, 256, pV2);
        node_attn_kernel<<<6250, 256>>>(src, dst, edge_feat, edge_times, te_w, te_phi, l);
        // agg2 = aggm @ We_v^T  (K=192)
        mma_gemm<0, false><<<dim3(GX, 2), 256, GSMEM_BYTES>>>(
            pAggm2, 192, 192, pWev2 + (size_t)l * 256 * 192, 192, 256,
            nullptr, pAgg2, 256, N_, 256, nullptr);
        node_update_kernel<<<6250, 256>>>(attn_ln_w + l * 256, attn_ln_b + l * 256,
                                          ln_w + l * 256, ln_b + l * 256);
    }

    // out = gelu(h @ out_w^T + out_b)
    mma_gemm<0, true><<<dim3(GX, 1), 256, GSMEM_BYTES>>>(
        ph2, 512, 512, pWout2, 512, 64, out_b, out, 64, N_, 64, nullptr);
}

// round 17
// speedup vs baseline: 1.0532x; 1.0530x over previous
#include <cuda_runtime.h>
#include <cuda_fp16.h>
#include <math.h>
#include <stdint.h>

static constexpr int N_ = 50000;
static constexpr int E_ = 200000;

// ---------------- scratch ----------------
__device__ __half  g_X2   [(size_t)N_ * 512];   // [hi|lo] fp16 split of [nf|mem]
__device__ float   g_h    [(size_t)N_ * 256];
__device__ __half  g_h2   [(size_t)N_ * 512];   // [hi|lo] split of h
__device__ float   g_hkvqp[(size_t)N_ * 1152];  // [K'(256)|Q'(256)|P(320)|V'(256)|pad]
__device__ float   g_agg  [(size_t)N_ * 256];
__device__ float   g_agg2 [(size_t)N_ * 256];
__device__ __half  g_aggm2[(size_t)N_ * 192];   // [hi80|lo80|pad32] fp16 split of aggm
__device__ float   g_nrm  [N_];
__device__ float   g_Wall [2 * 1152 * 256];     // fp32 [Wk;Wv;Wq;Wfused]
__device__ __half  g_Wkqp2[2 * 832 * 512];      // dup fp16 [Wk;Wq;Wfused]
__device__ __half  g_Wv2h [2 * 256 * 256];      // single fp16 Wv
__device__ float   g_bias_kqp[2 * 832];         // [bk|bq_eff|cb]
__device__ float   g_bias_v  [2 * 256];         // bv
__device__ __half  g_Win2 [256 * 512];
__device__ float   g_Wev  [2 * 256 * 80];
__device__ __half  g_Wev2 [2 * 256 * 192];
__device__ __half  g_Wout2[64 * 512];
__device__ float   g_b    [2 * 768];            // [bk|bv|bq_eff]
// CSR
__device__ int g_off [N_ + 1];
__device__ int g_cnt [N_];
__device__ int g_eid [E_];

// ---------------- ptx helpers (family-safe, sm_80 baseline) ----------------
__device__ __forceinline__ uint32_t smem_u32(const void* p) {
    uint32_t a;
    asm("{ .reg .u64 t; cvta.to.shared.u64 t, %1; cvt.u32.u64 %0, t; }" : "=r"(a) : "l"(p));
    return a;
}
__device__ __forceinline__ void cp16(uint32_t dst, const void* src, int pred) {
    asm volatile(
        "{\n\t.reg .pred p;\n\t"
        "setp.ne.u32 p, %2, 0;\n\t"
        "@p cp.async.ca.shared.global [%0], [%1], 16;\n\t"
        "@!p cp.async.ca.shared.global [%0], [%1], 16, 0;\n\t}"
        :: "r"(dst), "l"(src), "r"(pred) : "memory");
}
__device__ __forceinline__ void cp_commit() {
    asm volatile("cp.async.commit_group;" ::: "memory");
}
__device__ __forceinline__ void ldm4(uint32_t* r, uint32_t addr) {
    asm volatile("ldmatrix.sync.aligned.m8n8.x4.shared.b16 {%0,%1,%2,%3}, [%4];"
                 : "=r"(r[0]), "=r"(r[1]), "=r"(r[2]), "=r"(r[3]) : "r"(addr));
}
__device__ __forceinline__ void mma16816(float* c, const uint32_t* a, const uint32_t* b) {
    asm volatile(
        "mma.sync.aligned.m16n8k16.row.col.f32.f16.f16.f32 "
        "{%0,%1,%2,%3},{%4,%5,%6,%7},{%8,%9},{%0,%1,%2,%3};"
        : "+f"(c[0]), "+f"(c[1]), "+f"(c[2]), "+f"(c[3])
        : "r"(a[0]), "r"(a[1]), "r"(a[2]), "r"(a[3]), "r"(b[0]), "r"(b[1]));
}

// ---------------- mma.sync GEMM (double-buffered, K chunks of 64) ----------------
// MODE 0: plain fp32 C.  MODE 1: fp32 C + fp16 [hi|lo] split into S2.
// MODE 2 (KQP): col<256 -> fp16 into S2 (K'); col>=256 -> fp32 C at col-256 (Q'|P).
static constexpr int GSAS = 72;
static constexpr int GSEG = 128 * GSAS;
static constexpr int GSMEM_BYTES = 4 * GSEG * 2;  // 73728

template <int MODE, bool GELU>
__global__ __launch_bounds__(256)
void mma_gemm(const __half* __restrict__ A2, int lda, int klen,
              const __half* __restrict__ W2, int ldw, int noutW,
              const float* __restrict__ bias,
              float* __restrict__ C, int ldc, int M, int noutC,
              __half* __restrict__ S2) {
    extern __shared__ __align__(16) __half smem[];
    int tid = threadIdx.x, lane = tid & 31, wid = tid >> 5;
    int wm = wid & 1, wn = wid >> 1;
    int bm = blockIdx.x * 128, bn = blockIdx.y * 128;
    int NC = klen >> 6;
    uint32_t sU = smem_u32(smem);

    int arow = (lane & 7) + ((lane >> 3) & 1) * 8;
    int acol = ((lane >> 4) & 1) * 8;
    int bco  = ((lane >> 4) & 1) * 8 + (lane & 7);
    int bko  = ((lane >> 3) & 1) * 8;

    float acc[4][4][4] = {};

#define LOADC(c, buf)                                                                    \
    {                                                                                    \
        int _c64 = (c) * 64;                                                             \
        uint32_t _ab = sU + (buf) * (2 * GSEG * 2);                                      \
        uint32_t _bb = _ab + GSEG * 2;                                                   \
        _Pragma("unroll")                                                                \
        for (int _k = 0; _k < 4; _k++) {                                                 \
            int _id = tid + _k * 256;                                                    \
            int _r = _id >> 3, _cg = (_id & 7) * 8;                                      \
            uint32_t _so = (uint32_t)(_r * GSAS + _cg) * 2;                              \
            int _gr = bm + _r; int _pa = _gr < M; int _ga = _pa ? _gr : 0;               \
            cp16(_ab + _so, A2 + (size_t)_ga * lda + _c64 + _cg, _pa);                   \
            int _wr = bn + _r; int _pb = _wr < noutW; int _wa = _pb ? _wr : 0;           \
            cp16(_bb + _so, W2 + (size_t)_wa * ldw + _c64 + _cg, _pb);                   \
        }                                                                                \
        cp_commit();                                                                     \
    }

    LOADC(0, 0);
    for (int c = 0; c < NC; c++) {
        if (c + 1 < NC) {
            LOADC(c + 1, (c + 1) & 1);
            asm volatile("cp.async.wait_group 1;" ::: "memory");
        } else {
            asm volatile("cp.async.wait_group 0;" ::: "memory");
        }
        __syncthreads();
        uint32_t sAb = sU + (c & 1) * (2 * GSEG * 2);
        uint32_t sBb = sAb + GSEG * 2;
#pragma unroll
        for (int ks = 0; ks < 4; ks++) {
            uint32_t af[4][4];
#pragma unroll
            for (int mf = 0; mf < 4; mf++)
                ldm4(af[mf], sAb + (uint32_t)((wm * 64 + mf * 16 + arow) * GSAS + ks * 16 + acol) * 2);
            uint32_t bf[4][2];
#pragma unroll
            for (int p = 0; p < 2; p++) {
                uint32_t r4[4];
                ldm4(r4, sBb + (uint32_t)((wn * 32 + p * 16 + bco) * GSAS + ks * 16 + bko) * 2);
                bf[2 * p][0] = r4[0]; bf[2 * p][1] = r4[1];
                bf[2 * p + 1][0] = r4[2]; bf[2 * p + 1][1] = r4[3];
            }
#pragma unroll
            for (int mf = 0; mf < 4; mf++)
#pragma unroll
                for (int nf = 0; nf < 4; nf++)
                    mma16816(acc[mf][nf], af[mf], bf[nf]);
        }
        __syncthreads();
    }
#undef LOADC

    int cr = lane >> 2, cc = (lane & 3) * 2;
#pragma unroll
    for (int mf = 0; mf < 4; mf++) {
#pragma unroll
        for (int nf = 0; nf < 4; nf++) {
            int col = bn + wn * 32 + nf * 8 + cc;
            if (col >= noutC) continue;
            float bz0 = bias ? bias[col] : 0.f;
            float bz1 = bias ? bias[col + 1] : 0.f;
#pragma unroll
            for (int hh = 0; hh < 2; hh++) {
                int row = bm + wm * 64 + mf * 16 + cr + hh * 8;
                if (row >= M) continue;
                float v0 = acc[mf][nf][hh * 2 + 0] + bz0;
                float v1 = acc[mf][nf][hh * 2 + 1] + bz1;
                if (GELU) {
                    v0 = 0.5f * v0 * (1.0f + erff(v0 * 0.70710678118654752f));
                    v1 = 0.5f * v1 * (1.0f + erff(v1 * 0.70710678118654752f));
                }
                if (MODE == 2) {
                    if (col < 256) {
                        __half2 hv = __halves2half2(__float2half(v0), __float2half(v1));
                        *reinterpret_cast<__half2*>(S2 + (size_t)row * 256 + col) = hv;
                    } else {
                        *reinterpret_cast<float2*>(C + (size_t)row * ldc + (col - 256)) =
                            make_float2(v0, v1);
                    }
                } else {
                    *reinterpret_cast<float2*>(C + (size_t)row * ldc + col) = make_float2(v0, v1);
                    if (MODE == 1) {
                        size_t b2 = (size_t)row * 2 * noutC;
                        __half h0 = __float2half(v0);
                        __half l0 = __float2half(v0 - __half2float(h0));
                        __half h1 = __float2half(v1);
                        __half l1 = __float2half(v1 - __half2float(h1));
                        S2[b2 + col] = h0; S2[b2 + col + 1] = h1;
                        S2[b2 + noutC + col] = l0; S2[b2 + noutC + col + 1] = l1;
                    }
                }
            }
        }
    }
}

// ---------------- pack / conversion ----------------
__global__ void pack_x2_kernel(const float* __restrict__ nf, const float* __restrict__ mem) {
    int idx = blockIdx.x * blockDim.x + threadIdx.x;
    int stride = gridDim.x * blockDim.x;
    for (int i = idx; i < N_ * 256; i += stride) {
        int n = i >> 8, j = i & 255;
        float v = (j < 128) ? nf[n * 128 + j] : mem[n * 128 + (j - 128)];
        __half hi = __float2half(v);
        __half lo = __float2half(v - __half2float(hi));
        size_t b = (size_t)n * 512;
        g_X2[b + j] = hi; g_X2[b + 256 + j] = lo;
    }
}

__global__ void pack_b_kernel(const float* __restrict__ wk_b, const float* __restrict__ wv_b,
                              const float* __restrict__ wq_b, const float* __restrict__ wq_w,
                              const float* __restrict__ te_phi) {
    int idx = blockIdx.x * blockDim.x + threadIdx.x;
    if (idx >= 2 * 768) return;
    int l = idx / 768, r = idx % 768;
    float v;
    if (r < 256)      v = wk_b[l * 256 + r];
    else if (r < 512) v = wv_b[l * 256 + (r - 256)];
    else {
        int rq = r - 512;
        v = wq_b[l * 256 + rq];
        for (int t = 0; t < 16; t++) {
            float ph = te_phi[l * 16 + t];
            float qt = (t == 0) ? ph : sinf(ph);
            v += wq_w[(size_t)(l * 256 + rq) * 272 + 256 + t] * qt;
        }
    }
    g_b[idx] = v;
}

__global__ void pack_wall_base_kernel(const float* __restrict__ wk_w, const float* __restrict__ wv_w,
                                      const float* __restrict__ wq_w) {
    int idx = blockIdx.x * blockDim.x + threadIdx.x;
    int stride = gridDim.x * blockDim.x;
    for (int i = idx; i < 2 * 1088 * 256; i += stride) {
        int l = i / (1088 * 256); int r = (i / 256) % 1088; int k = i & 255;
        size_t o = (size_t)l * 1152 * 256 + (size_t)r * 256 + k;
        if (r < 256)      g_Wall[o] = wk_w[(size_t)(l * 256 + r)       * 336 + k];
        else if (r < 512) g_Wall[o] = wv_w[(size_t)(l * 256 + (r-256)) * 336 + k];
        else if (r < 768) g_Wall[o] = wq_w[(size_t)(l * 256 + (r-512)) * 272 + k];
    }
    for (int i = idx; i < 2 * 256 * 80; i += stride) {
        int l = i / (256 * 80); int r = (i / 80) % 256; int p = i % 80;
        g_Wev[i] = wv_w[(size_t)(l * 256 + r) * 336 + 256 + p];
    }
}

__global__ __launch_bounds__(256)
void pack_wall_fused_kernel(const float* __restrict__ wk_w, const float* __restrict__ wq_w) {
    __shared__ float wk_s[64];
    int b = blockIdx.x;               // 0..639
    int l = b / 320, q = b % 320;
    int hd = q / 80, p = q % 80;
    int t = threadIdx.x;
    if (t < 64) wk_s[t] = wk_w[(size_t)(l * 256 + 64 * hd + t) * 336 + 256 + p];
    __syncthreads();
    float acc = 0.f;
    for (int c = 0; c < 64; c++)
        acc += wk_s[c] * wq_w[(size_t)(l * 256 + 64 * hd + c) * 272 + t];
    g_Wall[(size_t)l * 1152 * 256 + (size_t)(768 + q) * 256 + t] = acc;
    if (t == 0) {
        float cb = 0.f;
        for (int c = 0; c < 64; c++) cb += wk_s[c] * g_b[l * 768 + 512 + 64 * hd + c];
        g_bias_kqp[l * 832 + 512 + q] = cb;
    }
}

__global__ void pack_bias_split_kernel() {
    int idx = blockIdx.x * blockDim.x + threadIdx.x;
    if (idx < 2 * 512) {
        int l = idx / 512, r = idx % 512;
        g_bias_kqp[l * 832 + r] = (r < 256) ? g_b[l * 768 + r] : g_b[l * 768 + 512 + (r - 256)];
    }
    if (idx < 2 * 256) {
        int l = idx / 256, r = idx % 256;
        g_bias_v[idx] = g_b[l * 768 + 256 + r];
    }
}

__global__ void conv_kqp_kernel() {
    int idx = blockIdx.x * blockDim.x + threadIdx.x;
    int stride = gridDim.x * blockDim.x;
    for (int i = idx; i < 2 * 832 * 512; i += stride) {
        int l = i / (832 * 512); int rem = i % (832 * 512);
        int r = rem / 512, j = rem % 512;
        int srcr = (r < 256) ? r : r + 256;
        float v = g_Wall[(size_t)l * 1152 * 256 + (size_t)srcr * 256 + (j < 256 ? j : j - 256)];
        g_Wkqp2[i] = __float2half(v);
    }
}

__global__ void conv_v_kernel() {
    int idx = blockIdx.x * blockDim.x + threadIdx.x;
    int stride = gridDim.x * blockDim.x;
    for (int i = idx; i < 2 * 256 * 256; i += stride) {
        int l = i / (256 * 256); int rem = i % (256 * 256);
        int r = rem / 256, j = rem % 256;
        g_Wv2h[i] = __float2half(g_Wall[(size_t)l * 1152 * 256 + (size_t)(256 + r) * 256 + j]);
    }
}

__global__ void conv_dup_kernel(const float* __restrict__ src, int rows, int K0,
                                __half* __restrict__ dst, int KA) {
    int idx = blockIdx.x * blockDim.x + threadIdx.x;
    int stride = gridDim.x * blockDim.x;
    long total = (long)rows * KA;
    for (long i = idx; i < total; i += stride) {
        int r = (int)(i / KA); int j = (int)(i % KA);
        float v = 0.f;
        if (j < 2 * K0) v = src[(size_t)r * K0 + (j < K0 ? j : j - K0)];
        dst[i] = __float2half(v);
    }
}

// ---------------- CSR build ----------------
__global__ void csr_zero_kernel() {
    int i = blockIdx.x * blockDim.x + threadIdx.x;
    if (i < N_) g_cnt[i] = 0;
}
__global__ void csr_count_kernel(const int* __restrict__ dst) {
    int e = blockIdx.x * blockDim.x + threadIdx.x;
    if (e < E_) atomicAdd(&g_cnt[dst[e]], 1);
}
__global__ __launch_bounds__(1024)
void csr_scan_kernel() {
    __shared__ int sh[1024];
    int tid = threadIdx.x;
    const int CH = (N_ + 1023) / 1024;   // 49
    int lo = tid * CH, hi = min(lo + CH, N_);
    int s = 0;
    for (int i = lo; i < hi; i++) s += g_cnt[i];
    sh[tid] = s;
    __syncthreads();
    for (int ofs = 1; ofs < 1024; ofs <<= 1) {
        int v = (tid >= ofs) ? sh[tid - ofs] : 0;
        __syncthreads();
        sh[tid] += v;
        __syncthreads();
    }
    int run = sh[tid] - s;   // exclusive prefix
    for (int i = lo; i < hi; i++) {
        g_off[i] = run;
        run += g_cnt[i];
        g_cnt[i] = 0;        // reset as fill cursor
    }
    if (tid == 1023) g_off[N_] = sh[1023];
}
__global__ void csr_fill_kernel(const int* __restrict__ dst) {
    int e = blockIdx.x * blockDim.x + threadIdx.x;
    if (e >= E_) return;
    int d = dst[e];
    int pos = atomicAdd(&g_cnt[d], 1);
    g_eid[g_off[d] + pos] = e;
}

// ---------------- node-centric attention (2-edge software pipeline) ----------------
// hkvqp layout: K' at +0, Q' at +256, P at +512, V' at +832
__global__ __launch_bounds__(256)
void node_attn_kernel(const int* __restrict__ src, const int* __restrict__ dst,
                      const float* __restrict__ ef, const float* __restrict__ et,
                      const float* __restrict__ te_w, const float* __restrict__ te_phi, int l) {
    int d = (blockIdx.x * blockDim.x + threadIdx.x) >> 5;
    int lane = threadIdx.x & 31;
    if (d >= N_) return;
    int jn = dst[d];                       // faithful h_dst[dst] quirk
    size_t jb = (size_t)jn * 1152;
    int o = lane * 8;
    int hl = lane & 7;

    float q[8];
    {
        float4 q0 = *reinterpret_cast<const float4*>(g_hkvqp + jb + 256 + o);
        float4 q1 = *reinterpret_cast<const float4*>(g_hkvqp + jb + 256 + o + 4);
        q[0]=q0.x; q[1]=q0.y; q[2]=q0.z; q[3]=q0.w; q[4]=q1.x; q[5]=q1.y; q[6]=q1.z; q[7]=q1.w;
    }
    float Pv[10];
    {
        const float* Pr = g_hkvqp + jb + 512 + (lane >> 3) * 80 + hl;
#pragma unroll
        for (int t = 0; t < 10; t++) Pv[t] = Pr[8 * t];
    }
    float tw = 0.f, tph = 0.f;
    if (lane < 16) { tw = te_w[l * 16 + lane]; tph = te_phi[l * 16 + lane]; }

    float aggv[8] = {};
    float am0 = 0.f, am1 = 0.f, am2 = 0.f;
    float nrm = 0.f;

    int beg = g_off[d], end = g_off[d + 1];
    int ii = beg;

    // ---- 2-edge pipelined main loop ----
    for (; ii + 1 < end; ii += 2) {
        int e0 = g_eid[ii], e1 = g_eid[ii + 1];
        int s0 = src[e0], s1 = src[e1];
        size_t sb0 = (size_t)s0 * 1152, sb1 = (size_t)s1 * 1152;
        const float* efp0 = ef + (size_t)e0 * 64;
        const float* efp1 = ef + (size_t)e1 * 64;

        // issue all gathers for both edges up front
        float4 k00 = *reinterpret_cast<const float4*>(g_hkvqp + sb0 + o);
        float4 k01 = *reinterpret_cast<const float4*>(g_hkvqp + sb0 + o + 4);
        float4 k10 = *reinterpret_cast<const float4*>(g_hkvqp + sb1 + o);
        float4 k11 = *reinterpret_cast<const float4*>(g_hkvqp + sb1 + o + 4);
        float4 v00 = *reinterpret_cast<const float4*>(g_hkvqp + sb0 + 832 + o);
        float4 v01 = *reinterpret_cast<const float4*>(g_hkvqp + sb0 + 832 + o + 4);
        float4 v10 = *reinterpret_cast<const float4*>(g_hkvqp + sb1 + 832 + o);
        float4 v11 = *reinterpret_cast<const float4*>(g_hkvqp + sb1 + 832 + o + 4);
        float te0 = et[e0], te1 = et[e1];

        float tv0 = 0.f, tv1 = 0.f;
        if (lane < 16) {
            float wt0 = -te0 * tw + tph;
            float wt1 = -te1 * tw + tph;
            tv0 = (lane == 0) ? wt0 : sinf(wt0);
            tv1 = (lane == 0) ? wt1 : sinf(wt1);
        }

        float a0 = k00.x * q[0] + k00.y * q[1] + k00.z * q[2] + k00.w * q[3]
                 + k01.x * q[4] + k01.y * q[5] + k01.z * q[6] + k01.w * q[7];
        float a1 = k10.x * q[0] + k10.y * q[1] + k10.z * q[2] + k10.w * q[3]
                 + k11.x * q[4] + k11.y * q[5] + k11.z * q[6] + k11.w * q[7];
#pragma unroll
        for (int t = 0; t < 8; t++) a0 += Pv[t] * efp0[hl + 8 * t];
#pragma unroll
        for (int t = 0; t < 8; t++) a1 += Pv[t] * efp1[hl + 8 * t];
        float t80 = __shfl_sync(0xffffffffu, tv0, hl);
        float t90 = __shfl_sync(0xffffffffu, tv0, hl + 8);
        float t81 = __shfl_sync(0xffffffffu, tv1, hl);
        float t91 = __shfl_sync(0xffffffffu, tv1, hl + 8);
        a0 += Pv[8] * t80 + Pv[9] * t90;
        a1 += Pv[8] * t81 + Pv[9] * t91;

        // independent shfl-reduction chains (pipeline)
        a0 += __shfl_xor_sync(0xffffffffu, a0, 1);
        a1 += __shfl_xor_sync(0xffffffffu, a1, 1);
        a0 += __shfl_xor_sync(0xffffffffu, a0, 2);
        a1 += __shfl_xor_sync(0xffffffffu, a1, 2);
        a0 += __shfl_xor_sync(0xffffffffu, a0, 4);
        a1 += __shfl_xor_sync(0xffffffffu, a1, 4);
        float sc0 = fminf(5.0f, fmaxf(-5.0f, a0 * 0.125f));
        float sc1 = fminf(5.0f, fmaxf(-5.0f, a1 * 0.125f));
        float x0 = __expf(sc0), x1 = __expf(sc1);
        float sm0 = x0, sm1 = x1;
        sm0 += __shfl_xor_sync(0xffffffffu, sm0, 8);
        sm1 += __shfl_xor_sync(0xffffffffu, sm1, 8);
        sm0 += __shfl_xor_sync(0xffffffffu, sm0, 16);
        sm1 += __shfl_xor_sync(0xffffffffu, sm1, 16);
        float af0 = sm0 * 0.25f, af1 = sm1 * 0.25f;

        aggv[0] += v00.x * af0 + v10.x * af1;
        aggv[1] += v00.y * af0 + v10.y * af1;
        aggv[2] += v00.z * af0 + v10.z * af1;
        aggv[3] += v00.w * af0 + v10.w * af1;
        aggv[4] += v01.x * af0 + v11.x * af1;
        aggv[5] += v01.y * af0 + v11.y * af1;
        aggv[6] += v01.z * af0 + v11.z * af1;
        aggv[7] += v01.w * af0 + v11.w * af1;
        am0 += efp0[lane] * af0 + efp1[lane] * af1;
        am1 += efp0[32 + lane] * af0 + efp1[32 + lane] * af1;
        if (lane < 16) am2 += tv0 * af0 + tv1 * af1;
        nrm += af0 + af1;
    }

    // ---- remainder (single edge) ----
    for (; ii < end; ii++) {
        int e = g_eid[ii];
        int s = src[e];
        size_t sb = (size_t)s * 1152;
        const float* efp = ef + (size_t)e * 64;

        float4 hk0 = *reinterpret_cast<const float4*>(g_hkvqp + sb + o);
        float4 hk1 = *reinterpret_cast<const float4*>(g_hkvqp + sb + o + 4);
        float4 hv0 = *reinterpret_cast<const float4*>(g_hkvqp + sb + 832 + o);
        float4 hv1 = *reinterpret_cast<const float4*>(g_hkvqp + sb + 832 + o + 4);

        float tv = 0.f;
        {
            float te = et[e];
            if (lane < 16) {
                float wt = -te * tw + tph;
                tv = (lane == 0) ? wt : sinf(wt);
            }
        }
        float acc = hk0.x * q[0] + hk0.y * q[1] + hk0.z * q[2] + hk0.w * q[3]
                  + hk1.x * q[4] + hk1.y * q[5] + hk1.z * q[6] + hk1.w * q[7];
#pragma unroll
        for (int t = 0; t < 8; t++) acc += Pv[t] * efp[hl + 8 * t];
        float t8 = __shfl_sync(0xffffffffu, tv, hl);
        float t9 = __shfl_sync(0xffffffffu, tv, hl + 8);
        acc += Pv[8] * t8 + Pv[9] * t9;

        acc += __shfl_xor_sync(0xffffffffu, acc, 1);
        acc += __shfl_xor_sync(0xffffffffu, acc, 2);
        acc += __shfl_xor_sync(0xffffffffu, acc, 4);
        float sc = fminf(5.0f, fmaxf(-5.0f, acc * 0.125f));
        float a = __expf(sc);
        float sm = a;
        sm += __shfl_xor_sync(0xffffffffu, sm, 8);
        sm += __shfl_xor_sync(0xffffffffu, sm, 16);
        float af = sm * 0.25f;

        aggv[0] += hv0.x * af; aggv[1] += hv0.y * af;
        aggv[2] += hv0.z * af; aggv[3] += hv0.w * af;
        aggv[4] += hv1.x * af; aggv[5] += hv1.y * af;
        aggv[6] += hv1.z * af; aggv[7] += hv1.w * af;
        am0 += efp[lane] * af;
        am1 += efp[32 + lane] * af;
        if (lane < 16) am2 += tv * af;
        nrm += af;
    }

    size_t base = (size_t)d * 256;
    *reinterpret_cast<float4*>(g_agg + base + o)     = make_float4(aggv[0], aggv[1], aggv[2], aggv[3]);
    *reinterpret_cast<float4*>(g_agg + base + o + 4) = make_float4(aggv[4], aggv[5], aggv[6], aggv[7]);
    if (lane == 0) g_nrm[d] = nrm;

    // aggm2: [hi(80) | lo(80) | pad(32, stays zero)]
    __half* am = g_aggm2 + (size_t)d * 192;
    {
        __half h0 = __float2half(am0);
        __half l0 = __float2half(am0 - __half2float(h0));
        am[lane] = h0; am[80 + lane] = l0;
        __half h1 = __float2half(am1);
        __half l1 = __float2half(am1 - __half2float(h1));
        am[32 + lane] = h1; am[112 + lane] = l1;
        if (lane < 16) {
            __half h2 = __float2half(am2);
            __half l2 = __float2half(am2 - __half2float(h2));
            am[64 + lane] = h2; am[144 + lane] = l2;
        }
    }
}

// ---------------- node update: h = LN(h + LN((agg+agg2)/(nrm+eps))); writes h and h2 ----------------
__global__ __launch_bounds__(256)
void node_update_kernel(const float* __restrict__ aw, const float* __restrict__ ab,
                        const float* __restrict__ lw, const float* __restrict__ lb) {
    int n = (blockIdx.x * blockDim.x + threadIdx.x) >> 5;
    int lane = threadIdx.x & 31;
    if (n >= N_) return;
    size_t base = (size_t)n * 256;
    int o = lane * 8;
    float inv = 1.0f / (g_nrm[n] + 1e-8f);
    float x[8];
    {
        float4 a0 = *reinterpret_cast<const float4*>(g_agg  + base + o);
        float4 a1 = *reinterpret_cast<const float4*>(g_agg  + base + o + 4);
        float4 b0 = *reinterpret_cast<const float4*>(g_agg2 + base + o);
        float4 b1 = *reinterpret_cast<const float4*>(g_agg2 + base + o + 4);
        x[0] = (a0.x + b0.x) * inv; x[1] = (a0.y + b0.y) * inv;
        x[2] = (a0.z + b0.z) * inv; x[3] = (a0.w + b0.w) * inv;
        x[4] = (a1.x + b1.x) * inv; x[5] = (a1.y + b1.y) * inv;
        x[6] = (a1.z + b1.z) * inv; x[7] = (a1.w + b1.w) * inv;
    }
    float s = 0.f;
#pragma unroll
    for (int i = 0; i < 8; i++) s += x[i];
#pragma unroll
    for (int m = 16; m >= 1; m >>= 1) s += __shfl_xor_sync(0xffffffffu, s, m);
    float mean = s * (1.0f / 256.0f);
    float vv = 0.f;
#pragma unroll
    for (int i = 0; i < 8; i++) { float dx = x[i] - mean; vv += dx * dx; }
#pragma unroll
    for (int m = 16; m >= 1; m >>= 1) vv += __shfl_xor_sync(0xffffffffu, vv, m);
    float is = rsqrtf(vv * (1.0f / 256.0f) + 1e-5f);
    float r[8];
#pragma unroll
    for (int i = 0; i < 8; i++) {
        float hn = (x[i] - mean) * is * aw[o + i] + ab[o + i];
        r[i] = g_h[base + o + i] + hn;
    }
    float s2 = 0.f;
#pragma unroll
    for (int i = 0; i < 8; i++) s2 += r[i];
#pragma unroll
    for (int m = 16; m >= 1; m >>= 1) s2 += __shfl_xor_sync(0xffffffffu, s2, m);
    float mean2 = s2 * (1.0f / 256.0f);
    float v2 = 0.f;
#pragma unroll
    for (int i = 0; i < 8; i++) { float dx = r[i] - mean2; v2 += dx * dx; }
#pragma unroll
    for (int m = 16; m >= 1; m >>= 1) v2 += __shfl_xor_sync(0xffffffffu, v2, m);
    float is2 = rsqrtf(v2 * (1.0f / 256.0f) + 1e-5f);
    size_t b2 = (size_t)n * 512;
#pragma unroll
    for (int i = 0; i < 8; i++) {
        float hv = (r[i] - mean2) * is2 * lw[o + i] + lb[o + i];
        g_h[base + o + i] = hv;
        __half hi = __float2half(hv);
        __half lo = __float2half(hv - __half2float(hi));
        g_h2[b2 + o + i] = hi;
        g_h2[b2 + 256 + o + i] = lo;
    }
}

// ---------------- launch ----------------
extern "C" void kernel_launch(void* const* d_in, const int* in_sizes, int n_in,
                              void* d_out, int out_size) {
    const float* node_feat  = (const float*)d_in[0];
    const float* memory     = (const float*)d_in[1];
    const int*   eidx       = (const int*)  d_in[2];
    const float* edge_feat  = (const float*)d_in[3];
    const float* edge_times = (const float*)d_in[4];
    const float* in_w       = (const float*)d_in[5];
    const float* in_b       = (const float*)d_in[6];
    const float* te_w       = (const float*)d_in[7];
    const float* te_phi     = (const float*)d_in[8];
    const float* wq_w       = (const float*)d_in[9];
    const float* wq_b       = (const float*)d_in[10];
    const float* wk_w       = (const float*)d_in[11];
    const float* wk_b       = (const float*)d_in[12];
    const float* wv_w       = (const float*)d_in[13];
    const float* wv_b       = (const float*)d_in[14];
    const float* attn_ln_w  = (const float*)d_in[15];
    const float* attn_ln_b  = (const float*)d_in[16];
    const float* ln_w       = (const float*)d_in[17];
    const float* ln_b       = (const float*)d_in[18];
    const float* out_w      = (const float*)d_in[19];
    const float* out_b      = (const float*)d_in[20];
    const int* src = eidx;
    const int* dst = eidx + E_;
    float* out = (float*)d_out;

    float *ph, *phkvqp, *pAgg2, *pWev, *pBiasKQP, *pBiasV;
    __half *pX2, *ph2, *pAggm2, *pWkqp2, *pWv2h, *pWin2, *pWev2, *pWout2;
    cudaGetSymbolAddress((void**)&ph,       g_h);
    cudaGetSymbolAddress((void**)&phkvqp,   g_hkvqp);
    cudaGetSymbolAddress((void**)&pAgg2,    g_agg2);
    cudaGetSymbolAddress((void**)&pWev,     g_Wev);
    cudaGetSymbolAddress((void**)&pBiasKQP, g_bias_kqp);
    cudaGetSymbolAddress((void**)&pBiasV,   g_bias_v);
    cudaGetSymbolAddress((void**)&pX2,      g_X2);
    cudaGetSymbolAddress((void**)&ph2,      g_h2);
    cudaGetSymbolAddress((void**)&pAggm2,   g_aggm2);
    cudaGetSymbolAddress((void**)&pWkqp2,   g_Wkqp2);
    cudaGetSymbolAddress((void**)&pWv2h,    g_Wv2h);
    cudaGetSymbolAddress((void**)&pWin2,    g_Win2);
    cudaGetSymbolAddress((void**)&pWev2,    g_Wev2);
    cudaGetSymbolAddress((void**)&pWout2,   g_Wout2);

    cudaFuncSetAttribute(mma_gemm<0, false>, cudaFuncAttributeMaxDynamicSharedMemorySize, GSMEM_BYTES);
    cudaFuncSetAttribute(mma_gemm<1, false>, cudaFuncAttributeMaxDynamicSharedMemorySize, GSMEM_BYTES);
    cudaFuncSetAttribute(mma_gemm<2, false>, cudaFuncAttributeMaxDynamicSharedMemorySize, GSMEM_BYTES);
    cudaFuncSetAttribute(mma_gemm<0, true>,  cudaFuncAttributeMaxDynamicSharedMemorySize, GSMEM_BYTES);

    const int GX = (N_ + 127) / 128;  // 391

    pack_x2_kernel<<<4096, 256>>>(node_feat, memory);
    pack_b_kernel<<<6, 256>>>(wk_b, wv_b, wq_b, wq_w, te_phi);
    pack_wall_base_kernel<<<2304, 256>>>(wk_w, wv_w, wq_w);
    pack_wall_fused_kernel<<<640, 256>>>(wk_w, wq_w);
    pack_bias_split_kernel<<<4, 256>>>();
    conv_kqp_kernel<<<1664, 256>>>();
    conv_v_kernel<<<512, 256>>>();
    conv_dup_kernel<<<512, 256>>>((const float*)in_w, 256, 256, pWin2, 512);
    conv_dup_kernel<<<128, 256>>>((const float*)out_w, 64, 256, pWout2, 512);
    conv_dup_kernel<<<384, 256>>>(pWev, 2 * 256, 80, pWev2, 192);

    // CSR build (topology is layer-independent)
    csr_zero_kernel<<<(N_ + 255) / 256, 256>>>();
    csr_count_kernel<<<(E_ + 255) / 256, 256>>>(dst);
    csr_scan_kernel<<<1, 1024>>>();
    csr_fill_kernel<<<(E_ + 255) / 256, 256>>>(dst);

    // h = X @ in_w^T + in_b (also emits h2 split)
    mma_gemm<1, false><<<dim3(GX, 2), 256, GSMEM_BYTES>>>(
        pX2, 512, 512, pWin2, 512, 256, in_b, ph, 256, N_, 256, ph2);

    for (int l = 0; l < 2; l++) {
        // [K'(fp32 in hkvqp? no: fp16? -> use MODE 2? no) ]
        // [K'|Q'|P] all fp32 into hkvqp via MODE 0 with bias; K' cols 0..255, Q' 256..511, P 512..831
        mma_gemm<0, false><<<dim3(GX, 7), 256, GSMEM_BYTES>>>(
            ph2, 512, 512, pWkqp2 + (size_t)l * 832 * 512, 512, 832,
            pBiasKQP + l * 832, phkvqp, 1152, N_, 832, nullptr);
        // V' = h_hi @ Wv^T + bv   (hi-only, K=256), fp32 at +832
        mma_gemm<0, false><<<dim3(GX, 2), 256, GSMEM_BYTES>>>(
            ph2, 512, 256, pWv2h + (size_t)l * 256 * 256, 256, 256,
            pBiasV + l * 256, phkvqp + 832, 1152, N_, 256, nullptr);
        node_attn_kernel<<<6250, 256>>>(src, dst, edge_feat, edge_times, te_w, te_phi, l);
        // agg2 = aggm @ We_v^T  (K=192)
        mma_gemm<0, false><<<dim3(GX, 2), 256, GSMEM_BYTES>>>(
            pAggm2, 192, 192, pWev2 + (size_t)l * 256 * 192, 192, 256,
            nullptr, pAgg2, 256, N_, 256, nullptr);
        node_update_kernel<<<6250, 256>>>(attn_ln_w + l * 256, attn_ln_b + l * 256,
                                          ln_w + l * 256, ln_b + l * 256);
    }

    // out = gelu(h @ out_w^T + out_b)
    mma_gemm<0, true><<<dim3(GX, 1), 256, GSMEM_BYTES>>>(
        ph2, 512, 512, pWout2, 512, 64, out_b, out, 64, N_, 64, nullptr);
}